// round 12
// baseline (speedup 1.0000x reference)
#include <cuda_runtime.h>
#include <cuda_bf16.h>
#include <cstdint>

#define TS   3584
#define DIM  1536
#define NH   12
#define HD   128
#define VS   1792
#define TPF  448
#define NW   28
#define EPS  1e-6f
#define SCALE 0.08838834764831845f   // 1/sqrt(128)

// -------- scratch (device globals; no allocations allowed) --------
__device__ float g_q[(size_t)TS * DIM];
__device__ float g_k[(size_t)TS * DIM];
__device__ __nv_bfloat16 g_xh[(size_t)TS * DIM];
__device__ __nv_bfloat16 g_xl[(size_t)TS * DIM];
__device__ __nv_bfloat16 g_qh[(size_t)TS * DIM];
__device__ __nv_bfloat16 g_ql[(size_t)TS * DIM];
__device__ __nv_bfloat16 g_kh[(size_t)TS * DIM];
__device__ __nv_bfloat16 g_kl[(size_t)TS * DIM];
__device__ __nv_bfloat16 g_vh[(size_t)TS * DIM];
__device__ __nv_bfloat16 g_vl[(size_t)TS * DIM];
__device__ __nv_bfloat16 g_oh[(size_t)TS * DIM];
__device__ __nv_bfloat16 g_ol[(size_t)TS * DIM];
__device__ __nv_bfloat16 g_wh[4][(size_t)DIM * DIM];
__device__ __nv_bfloat16 g_wl[4][(size_t)DIM * DIM];

// ======================= PTX helpers =======================
__device__ __forceinline__ uint32_t s2u(const void* p) {
    uint32_t a;
    asm("{ .reg .u64 t; cvta.to.shared.u64 t, %1; cvt.u32.u64 %0, t; }"
        : "=r"(a) : "l"(p));
    return a;
}
__device__ __forceinline__ void ldsm_x4(uint32_t* r, uint32_t addr) {
    asm volatile("ldmatrix.sync.aligned.m8n8.x4.shared.b16 {%0,%1,%2,%3}, [%4];"
                 : "=r"(r[0]), "=r"(r[1]), "=r"(r[2]), "=r"(r[3]) : "r"(addr));
}
__device__ __forceinline__ void ldsm_x4_t(uint32_t* r, uint32_t addr) {
    asm volatile("ldmatrix.sync.aligned.m8n8.x4.trans.shared.b16 {%0,%1,%2,%3}, [%4];"
                 : "=r"(r[0]), "=r"(r[1]), "=r"(r[2]), "=r"(r[3]) : "r"(addr));
}
__device__ __forceinline__ void mma16816(float* c, const uint32_t* a, const uint32_t* b) {
    asm volatile(
        "mma.sync.aligned.m16n8k16.row.col.f32.bf16.bf16.f32 "
        "{%0,%1,%2,%3}, {%4,%5,%6,%7}, {%8,%9}, {%0,%1,%2,%3};"
        : "+f"(c[0]), "+f"(c[1]), "+f"(c[2]), "+f"(c[3])
        : "r"(a[0]), "r"(a[1]), "r"(a[2]), "r"(a[3]), "r"(b[0]), "r"(b[1]));
}
__device__ __forceinline__ void cp16(uint32_t dst, const void* src) {
    asm volatile("cp.async.ca.shared.global [%0], [%1], 16;"
                 :: "r"(dst), "l"(src) : "memory");
}
__device__ __forceinline__ void cp_commit() {
    asm volatile("cp.async.commit_group;" ::: "memory");
}
template <int N>
__device__ __forceinline__ void cp_wait() {
    asm volatile("cp.async.wait_group %0;" :: "n"(N) : "memory");
}
__device__ __forceinline__ uint32_t packbf(float a, float b) {
    __nv_bfloat162 h;
    h.x = __float2bfloat16(a);
    h.y = __float2bfloat16(b);
    return *(uint32_t*)&h;
}

// ======================= fp32 -> (hi, lo) bf16 split (fused) ================
__device__ __forceinline__ void split_one(const float* __restrict__ in,
                                          __nv_bfloat16* __restrict__ hi,
                                          __nv_bfloat16* __restrict__ lo, int i) {
    float4 v = ((const float4*)in)[i];
    __nv_bfloat16 h0 = __float2bfloat16(v.x);
    __nv_bfloat16 h1 = __float2bfloat16(v.y);
    __nv_bfloat16 h2 = __float2bfloat16(v.z);
    __nv_bfloat16 h3 = __float2bfloat16(v.w);
    __nv_bfloat162 H0, H1, L0, L1;
    H0.x = h0; H0.y = h1; H1.x = h2; H1.y = h3;
    L0.x = __float2bfloat16(v.x - __bfloat162float(h0));
    L0.y = __float2bfloat16(v.y - __bfloat162float(h1));
    L1.x = __float2bfloat16(v.z - __bfloat162float(h2));
    L1.y = __float2bfloat16(v.w - __bfloat162float(h3));
    ((__nv_bfloat162*)hi)[2 * i]     = H0;
    ((__nv_bfloat162*)hi)[2 * i + 1] = H1;
    ((__nv_bfloat162*)lo)[2 * i]     = L0;
    ((__nv_bfloat162*)lo)[2 * i + 1] = L1;
}

#define NX4 (TS * DIM / 4)
#define NW4 (DIM * DIM / 4)

__global__ __launch_bounds__(256)
void split_all(const float* __restrict__ x,
               const float* __restrict__ qw, const float* __restrict__ kw,
               const float* __restrict__ vw, const float* __restrict__ ow,
               __nv_bfloat16* __restrict__ xh, __nv_bfloat16* __restrict__ xl,
               __nv_bfloat16* __restrict__ wh, __nv_bfloat16* __restrict__ wl) {
    int i = blockIdx.x * 256 + threadIdx.x;
    int z = blockIdx.y;
    if (z == 0) {
        if (i < NX4) split_one(x, xh, xl, i);
    } else {
        if (i < NW4) {
            const float* in = (z == 1) ? qw : (z == 2) ? kw : (z == 3) ? vw : ow;
            split_one(in, wh + (size_t)(z - 1) * DIM * DIM,
                          wl + (size_t)(z - 1) * DIM * DIM, i);
        }
    }
}

// ======================= mma.sync split-bf16 GEMM core ======================
// 256 threads, 8 warps (2M x 4N, 64x32 per warp), 2-stage cp.async ring.
// SSTR=40 (80B rows). 80KB smem -> 2 CTAs/SM.  (R10 WIN configuration)
#define SSTR 40
#define TILE_E (128 * SSTR)
#define TILE_B (TILE_E * 2)
#define BUF_E  (4 * TILE_E)
#define GNST 2
#define GEMM_SMEM_BYTES (GNST * BUF_E * 2)   // 81920

struct GemmOut {
    float acc[4][4][4];
};

__device__ __forceinline__ void gemm_core(
    const __nv_bfloat16* __restrict__ Ah, const __nv_bfloat16* __restrict__ Al,
    const __nv_bfloat16* __restrict__ Wh, const __nv_bfloat16* __restrict__ Wl,
    int m0, int n0, int K, __nv_bfloat16* sm, GemmOut& out) {
    const int tid  = threadIdx.x;
    const int warp = tid >> 5, lane = tid & 31;
    const int wm   = warp & 1;
    const int wn   = warp >> 1;
    const uint32_t sbase = s2u(sm);

#pragma unroll
    for (int i = 0; i < 4; i++)
#pragma unroll
        for (int j = 0; j < 4; j++)
#pragma unroll
            for (int k = 0; k < 4; k++) out.acc[i][j][k] = 0.f;

    const __nv_bfloat16* srcs[4] = {Ah, Al, Wh, Wl};

    auto issue_chunk = [&](int c, int s) {
#pragma unroll
        for (int j = 0; j < 8; j++) {
            int i = tid + j * 256;
            int arr = i >> 9;
            int idx = i & 511;
            int row = idx >> 2, seg = idx & 3;
            const __nv_bfloat16* src = srcs[arr] +
                (size_t)((arr < 2 ? m0 : n0) + row) * K + c * 32 + seg * 8;
            uint32_t dst = sbase + (uint32_t)(s * BUF_E + arr * TILE_E + row * SSTR + seg * 8) * 2;
            cp16(dst, src);
        }
        cp_commit();
    };

    const int NC = K / 32;
    issue_chunk(0, 0);

    const uint32_t arow = (uint32_t)(wm * 64 + (lane & 15));
    const uint32_t acol = (uint32_t)((lane >> 4) * 16);
    const uint32_t bro  = (uint32_t)((lane & 7) + 8 * ((lane >> 4) & 1));
    const uint32_t bco  = (uint32_t)(((lane >> 3) & 1) * 16);

    for (int c = 0; c < NC; c++) {
        cp_wait<0>();
        __syncthreads();
        if (c + 1 < NC) issue_chunk(c + 1, (c + 1) & 1);
        const uint32_t bb = sbase + (uint32_t)((c & 1) * BUF_E) * 2;
#pragma unroll
        for (int ks = 0; ks < 2; ks++) {
            uint32_t aH[4][4], aL[4][4], bH[8], bL[8];
            const uint32_t aoff = arow * (SSTR * 2) + ks * 32 + acol;
#pragma unroll
            for (int mt = 0; mt < 4; mt++)
                ldsm_x4(aH[mt], bb + 0 * TILE_B + aoff + mt * 16 * (SSTR * 2));
#pragma unroll
            for (int p = 0; p < 2; p++) {
                uint32_t boff = (uint32_t)(wn * 32 + p * 16 + bro) * (SSTR * 2) + ks * 32 + bco;
                ldsm_x4(&bH[4 * p], bb + 2 * TILE_B + boff);
            }
#pragma unroll
            for (int mt = 0; mt < 4; mt++)
#pragma unroll
                for (int nt = 0; nt < 4; nt++)
                    mma16816(out.acc[mt][nt], aH[mt], &bH[2 * nt]);
#pragma unroll
            for (int mt = 0; mt < 4; mt++)
                ldsm_x4(aL[mt], bb + 1 * TILE_B + aoff + mt * 16 * (SSTR * 2));
#pragma unroll
            for (int mt = 0; mt < 4; mt++)
#pragma unroll
                for (int nt = 0; nt < 4; nt++)
                    mma16816(out.acc[mt][nt], aL[mt], &bH[2 * nt]);
#pragma unroll
            for (int p = 0; p < 2; p++) {
                uint32_t boff = (uint32_t)(wn * 32 + p * 16 + bro) * (SSTR * 2) + ks * 32 + bco;
                ldsm_x4(&bL[4 * p], bb + 3 * TILE_B + boff);
            }
#pragma unroll
            for (int mt = 0; mt < 4; mt++)
#pragma unroll
                for (int nt = 0; nt < 4; nt++)
                    mma16816(out.acc[mt][nt], aH[mt], &bL[2 * nt]);
        }
    }
}

// ---- fused QKV projection: z = 0 (Q, f32) / 1 (K, f32) / 2 (V, bf16 hi/lo) ----
__global__ __launch_bounds__(256, 2)
void gemm_qkv(const __nv_bfloat16* __restrict__ xh, const __nv_bfloat16* __restrict__ xl,
              const __nv_bfloat16* __restrict__ whb, const __nv_bfloat16* __restrict__ wlb,
              const float* __restrict__ qb, const float* __restrict__ kb,
              const float* __restrict__ vb,
              float* __restrict__ gq, float* __restrict__ gk,
              __nv_bfloat16* __restrict__ vh, __nv_bfloat16* __restrict__ vl) {
    extern __shared__ __nv_bfloat16 sm[];
    const int z  = blockIdx.z;
    const int m0 = blockIdx.y * 128, n0 = blockIdx.x * 128;
    const size_t WSZ = (size_t)DIM * DIM;
    const __nv_bfloat16* Wh = whb + (size_t)z * WSZ;
    const __nv_bfloat16* Wl = wlb + (size_t)z * WSZ;
    const float* bias = (z == 0) ? qb : (z == 1) ? kb : vb;

    GemmOut out;
    gemm_core(xh, xl, Wh, Wl, m0, n0, DIM, sm, out);

    const int warp = threadIdx.x >> 5, lane = threadIdx.x & 31;
    const int row_base = m0 + (warp & 1) * 64 + (lane >> 2);
    const int col_base = n0 + (warp >> 1) * 32 + (lane & 3) * 2;
    float* Cf = (z == 0) ? gq : gk;
#pragma unroll
    for (int mt = 0; mt < 4; mt++) {
#pragma unroll
        for (int nt = 0; nt < 4; nt++) {
            int r = row_base + mt * 16;
            int cc = col_base + nt * 8;
            float bx = bias[cc], by = bias[cc + 1];
            float v00 = out.acc[mt][nt][0] + bx, v01 = out.acc[mt][nt][1] + by;
            float v10 = out.acc[mt][nt][2] + bx, v11 = out.acc[mt][nt][3] + by;
            if (z < 2) {
                *(float2*)(Cf + (size_t)r * DIM + cc)       = make_float2(v00, v01);
                *(float2*)(Cf + (size_t)(r + 8) * DIM + cc) = make_float2(v10, v11);
            } else {
                uint32_t h0 = packbf(v00, v01);
                uint32_t h1 = packbf(v10, v11);
                __nv_bfloat162 H0 = *(__nv_bfloat162*)&h0;
                __nv_bfloat162 H1 = *(__nv_bfloat162*)&h1;
                uint32_t l0 = packbf(v00 - __bfloat162float(H0.x), v01 - __bfloat162float(H0.y));
                uint32_t l1 = packbf(v10 - __bfloat162float(H1.x), v11 - __bfloat162float(H1.y));
                *(uint32_t*)(vh + (size_t)r * DIM + cc)       = h0;
                *(uint32_t*)(vh + (size_t)(r + 8) * DIM + cc) = h1;
                *(uint32_t*)(vl + (size_t)r * DIM + cc)       = l0;
                *(uint32_t*)(vl + (size_t)(r + 8) * DIM + cc) = l1;
            }
        }
    }
}

// ---- O projection (f32 out) ----
__global__ __launch_bounds__(256, 2)
void gemm_o(const __nv_bfloat16* __restrict__ Ah, const __nv_bfloat16* __restrict__ Al,
            const __nv_bfloat16* __restrict__ Wh, const __nv_bfloat16* __restrict__ Wl,
            const float* __restrict__ bias, float* __restrict__ Cf) {
    extern __shared__ __nv_bfloat16 sm[];
    const int m0 = blockIdx.y * 128, n0 = blockIdx.x * 128;
    GemmOut out;
    gemm_core(Ah, Al, Wh, Wl, m0, n0, DIM, sm, out);

    const int warp = threadIdx.x >> 5, lane = threadIdx.x & 31;
    const int row_base = m0 + (warp & 1) * 64 + (lane >> 2);
    const int col_base = n0 + (warp >> 1) * 32 + (lane & 3) * 2;
#pragma unroll
    for (int mt = 0; mt < 4; mt++) {
#pragma unroll
        for (int nt = 0; nt < 4; nt++) {
            int r = row_base + mt * 16;
            int cc = col_base + nt * 8;
            float bx = bias[cc], by = bias[cc + 1];
            *(float2*)(Cf + (size_t)r * DIM + cc) =
                make_float2(out.acc[mt][nt][0] + bx, out.acc[mt][nt][1] + by);
            *(float2*)(Cf + (size_t)(r + 8) * DIM + cc) =
                make_float2(out.acc[mt][nt][2] + bx, out.acc[mt][nt][3] + by);
        }
    }
}

// ======================= RMSNorm + RoPE -> bf16 hi/lo =======================
__global__ __launch_bounds__(256)
void norm_rope_kernel(const float* __restrict__ q, const float* __restrict__ k,
                      const float* __restrict__ freqs,
                      const float* __restrict__ nqw, const float* __restrict__ nkw,
                      __nv_bfloat16* __restrict__ QH, __nv_bfloat16* __restrict__ QL,
                      __nv_bfloat16* __restrict__ KH, __nv_bfloat16* __restrict__ KL) {
    const int row = blockIdx.x;
    const float* x = (blockIdx.y == 0 ? q : k) + (size_t)row * DIM;
    const float* w = (blockIdx.y == 0) ? nqw : nkw;
    __nv_bfloat16* OH = (blockIdx.y == 0) ? QH : KH;
    __nv_bfloat16* OL = (blockIdx.y == 0) ? QL : KL;
    const float sc = (blockIdx.y == 0) ? SCALE : 1.f;
    const int tid = threadIdx.x;

    float ss = 0.f;
    for (int i = tid; i < DIM; i += 256) { float v = x[i]; ss += v * v; }
#pragma unroll
    for (int o = 16; o > 0; o >>= 1) ss += __shfl_xor_sync(~0u, ss, o);
    __shared__ float warpsum[8];
    if ((tid & 31) == 0) warpsum[tid >> 5] = ss;
    __syncthreads();
    float tot = 0.f;
#pragma unroll
    for (int i = 0; i < 8; i++) tot += warpsum[i];
    const float rs = rsqrtf(tot / (float)DIM + EPS);

    const int tv = row % VS;
    const int f  = tv / TPF;
    const int r  = tv % TPF;
    const int hh = r / NW;
    const int ww = r % NW;

    for (int p = tid; p < DIM / 2; p += 256) {
        int c = p & 63;
        int idx = (c < 22) ? f : ((c < 43) ? hh : ww);
        float ang = freqs[idx * 64 + c];
        float sn, cs;
        sincosf(ang, &sn, &cs);
        float x0 = x[2 * p]     * rs * w[2 * p];
        float x1 = x[2 * p + 1] * rs * w[2 * p + 1];
        float r0 = (x0 * cs - x1 * sn) * sc;
        float r1 = (x0 * sn + x1 * cs) * sc;
        uint32_t h = packbf(r0, r1);
        __nv_bfloat162 H = *(__nv_bfloat162*)&h;
        uint32_t l = packbf(r0 - __bfloat162float(H.x), r1 - __bfloat162float(H.y));
        *(uint32_t*)(OH + (size_t)row * DIM + 2 * p) = h;
        *(uint32_t*)(OL + (size_t)row * DIM + 2 * p) = l;
    }
}

// ======================= mma.sync flash attention (key-split warp pairs) ====
// 64 queries x 1 head per block, 8 warps = 4 row-groups x 2 key-halves.
// QK uses TWO accumulator sets (Sa = QhKh; Sb = QhKl + QlKh) to double the
// number of independent HMMA dependency chains; summed at softmax (exact).
#define AQB  64
#define ASTR 136
#define AQR  (AQB * ASTR)          // 8704 elems
#define ATL  (32 * ASTR)           // 4352 elems
#define ASTAGE (4 * ATL)           // 17408 elems (34816 B)
#define ATT_SMEM_BYTES ((2 * AQR + 2 * ASTAGE) * 2)   // 104448

__global__ __launch_bounds__(256, 2)
void attn_mma(const __nv_bfloat16* __restrict__ Qh, const __nv_bfloat16* __restrict__ Ql,
              const __nv_bfloat16* __restrict__ Kh, const __nv_bfloat16* __restrict__ Kl,
              const __nv_bfloat16* __restrict__ Vh, const __nv_bfloat16* __restrict__ Vl,
              __nv_bfloat16* __restrict__ Oh, __nv_bfloat16* __restrict__ Ol) {
    extern __shared__ __nv_bfloat16 smb[];
    const uint32_t sbase = s2u(smb);
    const int head = blockIdx.y;
    const int q0   = blockIdx.x * AQB;
    const int v    = q0 / VS;
    const int f    = (q0 % VS) / TPF;      // uniform: 64 | 448
    const int col0 = head * HD;
    const int tid  = threadIdx.x;
    const int warp = tid >> 5, lane = tid & 31;
    const int g    = warp >> 1;            // row group (0..3), 16 rows each
    const int h    = warp & 1;             // key half (0..1), 16 keys each

    // ---- load Q tiles (hi/lo) into smem ----
    for (int i = tid; i < AQB * 16; i += 256) {
        int r = i >> 4, seg = i & 15;
        *(uint4*)&smb[r * ASTR + seg * 8] =
            *(const uint4*)&Qh[(size_t)(q0 + r) * DIM + col0 + seg * 8];
        *(uint4*)&smb[AQR + r * ASTR + seg * 8] =
            *(const uint4*)&Ql[(size_t)(q0 + r) * DIM + col0 + seg * 8];
    }

    const int baseA = v * VS;
    const int baseB = (1 - v) * VS + f * TPF;
    const int NT = 70;   // 56 same-view + 14 cross-view tiles

    const __nv_bfloat16* ptrs[4] = {Kh, Kl, Vh, Vl};

    auto issue_tile = [&](int t, int s) {
        int kb = (t < 56) ? (baseA + t * 32) : (baseB + (t - 56) * 32);
#pragma unroll
        for (int j = 0; j < 8; j++) {
            int i = tid + j * 256;
            int arr = i >> 9;
            int idx = i & 511;
            int r = idx >> 4, seg = idx & 15;
            const __nv_bfloat16* src = ptrs[arr] + (size_t)(kb + r) * DIM + col0 + seg * 8;
            uint32_t dst = sbase + (uint32_t)(2 * AQR + s * ASTAGE + arr * ATL + r * ASTR + seg * 8) * 2;
            cp16(dst, src);
        }
        cp_commit();
    };

    issue_tile(0, 0);

    float m[2] = {-1e30f, -1e30f};
    float l[2] = {0.f, 0.f};
    float acc[16][4];
#pragma unroll
    for (int nt = 0; nt < 16; nt++)
#pragma unroll
        for (int j = 0; j < 4; j++) acc[nt][j] = 0.f;

    const uint32_t q_goff = (uint32_t)(g * 16 + (lane & 15)) * (ASTR * 2)
                          + (uint32_t)((lane >> 4) * 16);
    const uint32_t k_bro  = (uint32_t)(h * 16 + (lane & 7) + 8 * ((lane >> 4) & 1));
    const uint32_t k_bco  = (uint32_t)(((lane >> 3) & 1) * 16);
    const uint32_t v_row  = (uint32_t)(h * 16 + (lane & 15));
    const uint32_t v_cofs = (uint32_t)(8 * ((lane >> 4) & 1));

    for (int t = 0; t < NT; t++) {
        cp_wait<0>();
        __syncthreads();
        if (t + 1 < NT) issue_tile(t + 1, (t + 1) & 1);

        const uint32_t st = sbase + (uint32_t)(2 * AQR + (t & 1) * ASTAGE) * 2;
        const uint32_t khb = st, klb = st + ATL * 2, vhb = st + 2 * ATL * 2, vlb = st + 3 * ATL * 2;

        // ---- S = Q K^T: two accumulator sets = 4 independent HMMA chains ----
        float Sa[2][4], Sb[2][4];
#pragma unroll
        for (int nt = 0; nt < 2; nt++)
#pragma unroll
            for (int j = 0; j < 4; j++) { Sa[nt][j] = 0.f; Sb[nt][j] = 0.f; }

#pragma unroll
        for (int ks = 0; ks < 8; ks++) {
            uint32_t aQh[4], aQl[4], bKh[4], bKl[4];
            ldsm_x4(aQh, sbase + q_goff + ks * 32);
            ldsm_x4(aQl, sbase + AQR * 2 + q_goff + ks * 32);
            uint32_t boff = k_bro * (ASTR * 2) + ks * 32 + k_bco;
            ldsm_x4(bKh, khb + boff);
            ldsm_x4(bKl, klb + boff);
            // grouped by destination: chains Sa[0],Sa[1],Sb[0],Sb[1]
            mma16816(Sa[0], aQh, &bKh[0]);
            mma16816(Sa[1], aQh, &bKh[2]);
            mma16816(Sb[0], aQh, &bKl[0]);
            mma16816(Sb[1], aQh, &bKl[2]);
            mma16816(Sb[0], aQl, &bKh[0]);
            mma16816(Sb[1], aQl, &bKh[2]);
        }

        float S[2][4];
#pragma unroll
        for (int nt = 0; nt < 2; nt++)
#pragma unroll
            for (int j = 0; j < 4; j++) S[nt][j] = Sa[nt][j] + Sb[nt][j];

        // ---- online softmax over this warp's keys ----
        float mn[2], corr[2];
#pragma unroll
        for (int j = 0; j < 2; j++) {
            float mx = fmaxf(fmaxf(S[0][2 * j], S[0][2 * j + 1]),
                             fmaxf(S[1][2 * j], S[1][2 * j + 1]));
            mx = fmaxf(mx, __shfl_xor_sync(~0u, mx, 1));
            mx = fmaxf(mx, __shfl_xor_sync(~0u, mx, 2));
            mn[j] = fmaxf(m[j], mx);
            corr[j] = __expf(m[j] - mn[j]);
        }
        bool resc = !__all_sync(~0u, (mn[0] == m[0]) && (mn[1] == m[1]));
        m[0] = mn[0]; m[1] = mn[1];

        uint32_t ph[2][2], pl[2][2];
#pragma unroll
        for (int j = 0; j < 2; j++) {
            float rs = 0.f;
#pragma unroll
            for (int nt = 0; nt < 2; nt++) {
                float e0 = __expf(S[nt][2 * j]     - mn[j]);
                float e1 = __expf(S[nt][2 * j + 1] - mn[j]);
                S[nt][2 * j] = e0; S[nt][2 * j + 1] = e1;
                rs += e0 + e1;
            }
            rs += __shfl_xor_sync(~0u, rs, 1);
            rs += __shfl_xor_sync(~0u, rs, 2);
            l[j] = l[j] * corr[j] + rs;
        }
        if (resc) {
#pragma unroll
            for (int nt = 0; nt < 16; nt++) {
                acc[nt][0] *= corr[0]; acc[nt][1] *= corr[0];
                acc[nt][2] *= corr[1]; acc[nt][3] *= corr[1];
            }
        }
#pragma unroll
        for (int nt = 0; nt < 2; nt++) {
#pragma unroll
            for (int j = 0; j < 2; j++) {
                float e0 = S[nt][2 * j], e1 = S[nt][2 * j + 1];
                uint32_t hh = packbf(e0, e1);
                __nv_bfloat162 H = *(__nv_bfloat162*)&hh;
                ph[nt][j] = hh;
                pl[nt][j] = packbf(e0 - __bfloat162float(H.x), e1 - __bfloat162float(H.y));
            }
        }

        // ---- out += P V over this warp's keys (3 split terms) ----
        uint32_t aPh[4] = {ph[0][0], ph[0][1], ph[1][0], ph[1][1]};
        uint32_t aPl[4] = {pl[0][0], pl[0][1], pl[1][0], pl[1][1]};
#pragma unroll
        for (int dp = 0; dp < 8; dp++) {
            uint32_t bVh[4], bVl[4];
            uint32_t voff = v_row * (ASTR * 2) + (uint32_t)(dp * 16 + v_cofs) * 2;
            ldsm_x4_t(bVh, vhb + voff);
            mma16816(acc[2 * dp],     aPh, &bVh[0]);
            mma16816(acc[2 * dp + 1], aPh, &bVh[2]);
            mma16816(acc[2 * dp],     aPl, &bVh[0]);
            mma16816(acc[2 * dp + 1], aPl, &bVh[2]);
            ldsm_x4_t(bVl, vlb + voff);
            mma16816(acc[2 * dp],     aPh, &bVl[0]);
            mma16816(acc[2 * dp + 1], aPh, &bVl[2]);
        }
    }

    // ---- merge warp pairs (h=1 publishes, h=0 combines) ----
    __syncthreads();
    float* ex = (float*)smb;
    if (h == 1) {
        float* d = ex + (g * 32 + lane) * 68;
        d[0] = m[0]; d[1] = m[1]; d[2] = l[0]; d[3] = l[1];
#pragma unroll
        for (int nt = 0; nt < 16; nt++) {
            d[4 + 4 * nt + 0] = acc[nt][0];
            d[4 + 4 * nt + 1] = acc[nt][1];
            d[4 + 4 * nt + 2] = acc[nt][2];
            d[4 + 4 * nt + 3] = acc[nt][3];
        }
    }
    __syncthreads();
    if (h == 0) {
        const float* d = ex + (g * 32 + lane) * 68;
        float pm[2] = {d[0], d[1]};
        float pll[2] = {d[2], d[3]};
        float a[2], b[2], inv[2];
#pragma unroll
        for (int j = 0; j < 2; j++) {
            float M = fmaxf(m[j], pm[j]);
            a[j] = __expf(m[j] - M);
            b[j] = __expf(pm[j] - M);
            inv[j] = 1.f / (a[j] * l[j] + b[j] * pll[j]);
        }
#pragma unroll
        for (int j = 0; j < 2; j++) {
            int row = q0 + g * 16 + (lane >> 2) + 8 * j;
#pragma unroll
            for (int nt = 0; nt < 16; nt++) {
                float o0 = (a[j] * acc[nt][2 * j]     + b[j] * d[4 + 4 * nt + 2 * j])     * inv[j];
                float o1 = (a[j] * acc[nt][2 * j + 1] + b[j] * d[4 + 4 * nt + 2 * j + 1]) * inv[j];
                uint32_t hh = packbf(o0, o1);
                __nv_bfloat162 H = *(__nv_bfloat162*)&hh;
                uint32_t lo = packbf(o0 - __bfloat162float(H.x), o1 - __bfloat162float(H.y));
                size_t off = (size_t)row * DIM + col0 + nt * 8 + 2 * (lane & 3);
                *(uint32_t*)(Oh + off) = hh;
                *(uint32_t*)(Ol + off) = lo;
            }
        }
    }
}

// ======================= launch =======================
extern "C" void kernel_launch(void* const* d_in, const int* in_sizes, int n_in,
                              void* d_out, int out_size) {
    const float* x     = (const float*)d_in[0];
    const float* freqs = (const float*)d_in[1];
    const float* q_w   = (const float*)d_in[2];
    const float* q_b   = (const float*)d_in[3];
    const float* k_w   = (const float*)d_in[4];
    const float* k_b   = (const float*)d_in[5];
    const float* v_w   = (const float*)d_in[6];
    const float* v_b   = (const float*)d_in[7];
    const float* o_w   = (const float*)d_in[8];
    const float* o_b   = (const float*)d_in[9];
    const float* nqw   = (const float*)d_in[10];
    const float* nkw   = (const float*)d_in[11];

    float *gq, *gk;
    __nv_bfloat16 *xh, *xl, *qh, *ql, *kh, *kl, *vh, *vl, *oh, *ol, *wh, *wl;
    cudaGetSymbolAddress((void**)&gq, g_q);
    cudaGetSymbolAddress((void**)&gk, g_k);
    cudaGetSymbolAddress((void**)&xh, g_xh);
    cudaGetSymbolAddress((void**)&xl, g_xl);
    cudaGetSymbolAddress((void**)&qh, g_qh);
    cudaGetSymbolAddress((void**)&ql, g_ql);
    cudaGetSymbolAddress((void**)&kh, g_kh);
    cudaGetSymbolAddress((void**)&kl, g_kl);
    cudaGetSymbolAddress((void**)&vh, g_vh);
    cudaGetSymbolAddress((void**)&vl, g_vl);
    cudaGetSymbolAddress((void**)&oh, g_oh);
    cudaGetSymbolAddress((void**)&ol, g_ol);
    cudaGetSymbolAddress((void**)&wh, g_wh);
    cudaGetSymbolAddress((void**)&wl, g_wl);

    const size_t WSZ = (size_t)DIM * DIM;
    __nv_bfloat16 *owh = wh + 3 * WSZ, *owl = wl + 3 * WSZ;

    split_all<<<dim3((NX4 + 255) / 256, 5), 256>>>(x, q_w, k_w, v_w, o_w, xh, xl, wh, wl);

    cudaFuncSetAttribute(gemm_qkv, cudaFuncAttributeMaxDynamicSharedMemorySize,
                         GEMM_SMEM_BYTES);
    cudaFuncSetAttribute(gemm_o, cudaFuncAttributeMaxDynamicSharedMemorySize,
                         GEMM_SMEM_BYTES);
    gemm_qkv<<<dim3(DIM / 128, TS / 128, 3), 256, GEMM_SMEM_BYTES>>>(
        xh, xl, wh, wl, q_b, k_b, v_b, gq, gk, vh, vl);

    norm_rope_kernel<<<dim3(TS, 2), 256>>>(gq, gk, freqs, nqw, nkw, qh, ql, kh, kl);

    cudaFuncSetAttribute(attn_mma, cudaFuncAttributeMaxDynamicSharedMemorySize,
                         ATT_SMEM_BYTES);
    attn_mma<<<dim3(TS / AQB, NH), 256, ATT_SMEM_BYTES>>>(qh, ql, kh, kl, vh, vl, oh, ol);

    gemm_o<<<dim3(DIM / 128, TS / 128), 256, GEMM_SMEM_BYTES>>>(
        oh, ol, owh, owl, o_b, (float*)d_out);
}

// round 13
// speedup vs baseline: 1.1635x; 1.1635x over previous
#include <cuda_runtime.h>
#include <cuda_bf16.h>
#include <cuda_fp16.h>
#include <cstdint>

#define TS   3584
#define DIM  1536
#define NH   12
#define HD   128
#define VS   1792
#define TPF  448
#define NW   28
#define EPS  1e-6f
#define SCALE 0.08838834764831845f   // 1/sqrt(128)

// -------- scratch (device globals; no allocations allowed) --------
__device__ float g_q[(size_t)TS * DIM];
__device__ float g_k[(size_t)TS * DIM];
__device__ __nv_bfloat16 g_xh[(size_t)TS * DIM];
__device__ __nv_bfloat16 g_xl[(size_t)TS * DIM];
__device__ __half g_qf[(size_t)TS * DIM];    // Q single fp16 (pre-scaled)
__device__ __half g_kfh[(size_t)TS * DIM];   // K fp16 hi
__device__ __half g_kfl[(size_t)TS * DIM];   // K fp16 lo
__device__ __half g_vf[(size_t)TS * DIM];    // V single fp16
__device__ __nv_bfloat16 g_oh[(size_t)TS * DIM];
__device__ __nv_bfloat16 g_ol[(size_t)TS * DIM];
__device__ __nv_bfloat16 g_wh[4][(size_t)DIM * DIM];
__device__ __nv_bfloat16 g_wl[4][(size_t)DIM * DIM];

// ======================= PTX helpers =======================
__device__ __forceinline__ uint32_t s2u(const void* p) {
    uint32_t a;
    asm("{ .reg .u64 t; cvta.to.shared.u64 t, %1; cvt.u32.u64 %0, t; }"
        : "=r"(a) : "l"(p));
    return a;
}
__device__ __forceinline__ void ldsm_x4(uint32_t* r, uint32_t addr) {
    asm volatile("ldmatrix.sync.aligned.m8n8.x4.shared.b16 {%0,%1,%2,%3}, [%4];"
                 : "=r"(r[0]), "=r"(r[1]), "=r"(r[2]), "=r"(r[3]) : "r"(addr));
}
__device__ __forceinline__ void ldsm_x4_t(uint32_t* r, uint32_t addr) {
    asm volatile("ldmatrix.sync.aligned.m8n8.x4.trans.shared.b16 {%0,%1,%2,%3}, [%4];"
                 : "=r"(r[0]), "=r"(r[1]), "=r"(r[2]), "=r"(r[3]) : "r"(addr));
}
__device__ __forceinline__ void mma16816(float* c, const uint32_t* a, const uint32_t* b) {
    asm volatile(
        "mma.sync.aligned.m16n8k16.row.col.f32.bf16.bf16.f32 "
        "{%0,%1,%2,%3}, {%4,%5,%6,%7}, {%8,%9}, {%0,%1,%2,%3};"
        : "+f"(c[0]), "+f"(c[1]), "+f"(c[2]), "+f"(c[3])
        : "r"(a[0]), "r"(a[1]), "r"(a[2]), "r"(a[3]), "r"(b[0]), "r"(b[1]));
}
__device__ __forceinline__ void mma16816h(float* c, const uint32_t* a, const uint32_t* b) {
    asm volatile(
        "mma.sync.aligned.m16n8k16.row.col.f32.f16.f16.f32 "
        "{%0,%1,%2,%3}, {%4,%5,%6,%7}, {%8,%9}, {%0,%1,%2,%3};"
        : "+f"(c[0]), "+f"(c[1]), "+f"(c[2]), "+f"(c[3])
        : "r"(a[0]), "r"(a[1]), "r"(a[2]), "r"(a[3]), "r"(b[0]), "r"(b[1]));
}
__device__ __forceinline__ void cp16(uint32_t dst, const void* src) {
    asm volatile("cp.async.ca.shared.global [%0], [%1], 16;"
                 :: "r"(dst), "l"(src) : "memory");
}
__device__ __forceinline__ void cp_commit() {
    asm volatile("cp.async.commit_group;" ::: "memory");
}
template <int N>
__device__ __forceinline__ void cp_wait() {
    asm volatile("cp.async.wait_group %0;" :: "n"(N) : "memory");
}
__device__ __forceinline__ uint32_t packbf(float a, float b) {
    __nv_bfloat162 h;
    h.x = __float2bfloat16(a);
    h.y = __float2bfloat16(b);
    return *(uint32_t*)&h;
}
__device__ __forceinline__ uint32_t packh(float a, float b) {
    __half2 h = __floats2half2_rn(a, b);
    return *(uint32_t*)&h;
}

// ======================= fp32 -> (hi, lo) bf16 split (fused) ================
__device__ __forceinline__ void split_one(const float* __restrict__ in,
                                          __nv_bfloat16* __restrict__ hi,
                                          __nv_bfloat16* __restrict__ lo, int i) {
    float4 v = ((const float4*)in)[i];
    __nv_bfloat16 h0 = __float2bfloat16(v.x);
    __nv_bfloat16 h1 = __float2bfloat16(v.y);
    __nv_bfloat16 h2 = __float2bfloat16(v.z);
    __nv_bfloat16 h3 = __float2bfloat16(v.w);
    __nv_bfloat162 H0, H1, L0, L1;
    H0.x = h0; H0.y = h1; H1.x = h2; H1.y = h3;
    L0.x = __float2bfloat16(v.x - __bfloat162float(h0));
    L0.y = __float2bfloat16(v.y - __bfloat162float(h1));
    L1.x = __float2bfloat16(v.z - __bfloat162float(h2));
    L1.y = __float2bfloat16(v.w - __bfloat162float(h3));
    ((__nv_bfloat162*)hi)[2 * i]     = H0;
    ((__nv_bfloat162*)hi)[2 * i + 1] = H1;
    ((__nv_bfloat162*)lo)[2 * i]     = L0;
    ((__nv_bfloat162*)lo)[2 * i + 1] = L1;
}

#define NX4 (TS * DIM / 4)
#define NW4 (DIM * DIM / 4)

__global__ __launch_bounds__(256)
void split_all(const float* __restrict__ x,
               const float* __restrict__ qw, const float* __restrict__ kw,
               const float* __restrict__ vw, const float* __restrict__ ow,
               __nv_bfloat16* __restrict__ xh, __nv_bfloat16* __restrict__ xl,
               __nv_bfloat16* __restrict__ wh, __nv_bfloat16* __restrict__ wl) {
    int i = blockIdx.x * 256 + threadIdx.x;
    int z = blockIdx.y;
    if (z == 0) {
        if (i < NX4) split_one(x, xh, xl, i);
    } else {
        if (i < NW4) {
            const float* in = (z == 1) ? qw : (z == 2) ? kw : (z == 3) ? vw : ow;
            split_one(in, wh + (size_t)(z - 1) * DIM * DIM,
                          wl + (size_t)(z - 1) * DIM * DIM, i);
        }
    }
}

// ======================= mma.sync split-bf16 GEMM core ======================
// 256 threads, 8 warps (2M x 4N, 64x32 per warp), 2-stage cp.async ring.
// SSTR=40 (80B rows). 80KB smem -> 2 CTAs/SM.  (R10 WIN configuration)
#define SSTR 40
#define TILE_E (128 * SSTR)
#define TILE_B (TILE_E * 2)
#define BUF_E  (4 * TILE_E)
#define GNST 2
#define GEMM_SMEM_BYTES (GNST * BUF_E * 2)   // 81920

struct GemmOut {
    float acc[4][4][4];
};

__device__ __forceinline__ void gemm_core(
    const __nv_bfloat16* __restrict__ Ah, const __nv_bfloat16* __restrict__ Al,
    const __nv_bfloat16* __restrict__ Wh, const __nv_bfloat16* __restrict__ Wl,
    int m0, int n0, int K, __nv_bfloat16* sm, GemmOut& out) {
    const int tid  = threadIdx.x;
    const int warp = tid >> 5, lane = tid & 31;
    const int wm   = warp & 1;
    const int wn   = warp >> 1;
    const uint32_t sbase = s2u(sm);

#pragma unroll
    for (int i = 0; i < 4; i++)
#pragma unroll
        for (int j = 0; j < 4; j++)
#pragma unroll
            for (int k = 0; k < 4; k++) out.acc[i][j][k] = 0.f;

    const __nv_bfloat16* srcs[4] = {Ah, Al, Wh, Wl};

    auto issue_chunk = [&](int c, int s) {
#pragma unroll
        for (int j = 0; j < 8; j++) {
            int i = tid + j * 256;
            int arr = i >> 9;
            int idx = i & 511;
            int row = idx >> 2, seg = idx & 3;
            const __nv_bfloat16* src = srcs[arr] +
                (size_t)((arr < 2 ? m0 : n0) + row) * K + c * 32 + seg * 8;
            uint32_t dst = sbase + (uint32_t)(s * BUF_E + arr * TILE_E + row * SSTR + seg * 8) * 2;
            cp16(dst, src);
        }
        cp_commit();
    };

    const int NC = K / 32;
    issue_chunk(0, 0);

    const uint32_t arow = (uint32_t)(wm * 64 + (lane & 15));
    const uint32_t acol = (uint32_t)((lane >> 4) * 16);
    const uint32_t bro  = (uint32_t)((lane & 7) + 8 * ((lane >> 4) & 1));
    const uint32_t bco  = (uint32_t)(((lane >> 3) & 1) * 16);

    for (int c = 0; c < NC; c++) {
        cp_wait<0>();
        __syncthreads();
        if (c + 1 < NC) issue_chunk(c + 1, (c + 1) & 1);
        const uint32_t bb = sbase + (uint32_t)((c & 1) * BUF_E) * 2;
#pragma unroll
        for (int ks = 0; ks < 2; ks++) {
            uint32_t aH[4][4], aL[4][4], bH[8], bL[8];
            const uint32_t aoff = arow * (SSTR * 2) + ks * 32 + acol;
#pragma unroll
            for (int mt = 0; mt < 4; mt++)
                ldsm_x4(aH[mt], bb + 0 * TILE_B + aoff + mt * 16 * (SSTR * 2));
#pragma unroll
            for (int p = 0; p < 2; p++) {
                uint32_t boff = (uint32_t)(wn * 32 + p * 16 + bro) * (SSTR * 2) + ks * 32 + bco;
                ldsm_x4(&bH[4 * p], bb + 2 * TILE_B + boff);
            }
#pragma unroll
            for (int mt = 0; mt < 4; mt++)
#pragma unroll
                for (int nt = 0; nt < 4; nt++)
                    mma16816(out.acc[mt][nt], aH[mt], &bH[2 * nt]);
#pragma unroll
            for (int mt = 0; mt < 4; mt++)
                ldsm_x4(aL[mt], bb + 1 * TILE_B + aoff + mt * 16 * (SSTR * 2));
#pragma unroll
            for (int mt = 0; mt < 4; mt++)
#pragma unroll
                for (int nt = 0; nt < 4; nt++)
                    mma16816(out.acc[mt][nt], aL[mt], &bH[2 * nt]);
#pragma unroll
            for (int p = 0; p < 2; p++) {
                uint32_t boff = (uint32_t)(wn * 32 + p * 16 + bro) * (SSTR * 2) + ks * 32 + bco;
                ldsm_x4(&bL[4 * p], bb + 3 * TILE_B + boff);
            }
#pragma unroll
            for (int mt = 0; mt < 4; mt++)
#pragma unroll
                for (int nt = 0; nt < 4; nt++)
                    mma16816(out.acc[mt][nt], aH[mt], &bL[2 * nt]);
        }
    }
}

// ---- fused QKV projection: z = 0 (Q, f32) / 1 (K, f32) / 2 (V, single fp16) --
__global__ __launch_bounds__(256, 2)
void gemm_qkv(const __nv_bfloat16* __restrict__ xh, const __nv_bfloat16* __restrict__ xl,
              const __nv_bfloat16* __restrict__ whb, const __nv_bfloat16* __restrict__ wlb,
              const float* __restrict__ qb, const float* __restrict__ kb,
              const float* __restrict__ vb,
              float* __restrict__ gq, float* __restrict__ gk,
              __half* __restrict__ vf) {
    extern __shared__ __nv_bfloat16 sm[];
    const int z  = blockIdx.z;
    const int m0 = blockIdx.y * 128, n0 = blockIdx.x * 128;
    const size_t WSZ = (size_t)DIM * DIM;
    const __nv_bfloat16* Wh = whb + (size_t)z * WSZ;
    const __nv_bfloat16* Wl = wlb + (size_t)z * WSZ;
    const float* bias = (z == 0) ? qb : (z == 1) ? kb : vb;

    GemmOut out;
    gemm_core(xh, xl, Wh, Wl, m0, n0, DIM, sm, out);

    const int warp = threadIdx.x >> 5, lane = threadIdx.x & 31;
    const int row_base = m0 + (warp & 1) * 64 + (lane >> 2);
    const int col_base = n0 + (warp >> 1) * 32 + (lane & 3) * 2;
    float* Cf = (z == 0) ? gq : gk;
#pragma unroll
    for (int mt = 0; mt < 4; mt++) {
#pragma unroll
        for (int nt = 0; nt < 4; nt++) {
            int r = row_base + mt * 16;
            int cc = col_base + nt * 8;
            float bx = bias[cc], by = bias[cc + 1];
            float v00 = out.acc[mt][nt][0] + bx, v01 = out.acc[mt][nt][1] + by;
            float v10 = out.acc[mt][nt][2] + bx, v11 = out.acc[mt][nt][3] + by;
            if (z < 2) {
                *(float2*)(Cf + (size_t)r * DIM + cc)       = make_float2(v00, v01);
                *(float2*)(Cf + (size_t)(r + 8) * DIM + cc) = make_float2(v10, v11);
            } else {
                *(uint32_t*)(vf + (size_t)r * DIM + cc)       = packh(v00, v01);
                *(uint32_t*)(vf + (size_t)(r + 8) * DIM + cc) = packh(v10, v11);
            }
        }
    }
}

// ---- O projection (f32 out) ----
__global__ __launch_bounds__(256, 2)
void gemm_o(const __nv_bfloat16* __restrict__ Ah, const __nv_bfloat16* __restrict__ Al,
            const __nv_bfloat16* __restrict__ Wh, const __nv_bfloat16* __restrict__ Wl,
            const float* __restrict__ bias, float* __restrict__ Cf) {
    extern __shared__ __nv_bfloat16 sm[];
    const int m0 = blockIdx.y * 128, n0 = blockIdx.x * 128;
    GemmOut out;
    gemm_core(Ah, Al, Wh, Wl, m0, n0, DIM, sm, out);

    const int warp = threadIdx.x >> 5, lane = threadIdx.x & 31;
    const int row_base = m0 + (warp & 1) * 64 + (lane >> 2);
    const int col_base = n0 + (warp >> 1) * 32 + (lane & 3) * 2;
#pragma unroll
    for (int mt = 0; mt < 4; mt++) {
#pragma unroll
        for (int nt = 0; nt < 4; nt++) {
            int r = row_base + mt * 16;
            int cc = col_base + nt * 8;
            float bx = bias[cc], by = bias[cc + 1];
            *(float2*)(Cf + (size_t)r * DIM + cc) =
                make_float2(out.acc[mt][nt][0] + bx, out.acc[mt][nt][1] + by);
            *(float2*)(Cf + (size_t)(r + 8) * DIM + cc) =
                make_float2(out.acc[mt][nt][2] + bx, out.acc[mt][nt][3] + by);
        }
    }
}

// ======================= RMSNorm + RoPE =======================
// Q -> single fp16 (pre-scaled by SCALE).  K -> fp16 hi/lo.
__global__ __launch_bounds__(256)
void norm_rope_kernel(const float* __restrict__ q, const float* __restrict__ k,
                      const float* __restrict__ freqs,
                      const float* __restrict__ nqw, const float* __restrict__ nkw,
                      __half* __restrict__ QF,
                      __half* __restrict__ KFH, __half* __restrict__ KFL) {
    const int row = blockIdx.x;
    const int isq = (blockIdx.y == 0);
    const float* x = (isq ? q : k) + (size_t)row * DIM;
    const float* w = isq ? nqw : nkw;
    const float sc = isq ? SCALE : 1.f;
    const int tid = threadIdx.x;

    float ss = 0.f;
    for (int i = tid; i < DIM; i += 256) { float v = x[i]; ss += v * v; }
#pragma unroll
    for (int o = 16; o > 0; o >>= 1) ss += __shfl_xor_sync(~0u, ss, o);
    __shared__ float warpsum[8];
    if ((tid & 31) == 0) warpsum[tid >> 5] = ss;
    __syncthreads();
    float tot = 0.f;
#pragma unroll
    for (int i = 0; i < 8; i++) tot += warpsum[i];
    const float rs = rsqrtf(tot / (float)DIM + EPS);

    const int tv = row % VS;
    const int f  = tv / TPF;
    const int r  = tv % TPF;
    const int hh = r / NW;
    const int ww = r % NW;

    for (int p = tid; p < DIM / 2; p += 256) {
        int c = p & 63;
        int idx = (c < 22) ? f : ((c < 43) ? hh : ww);
        float ang = freqs[idx * 64 + c];
        float sn, cs;
        sincosf(ang, &sn, &cs);
        float x0 = x[2 * p]     * rs * w[2 * p];
        float x1 = x[2 * p + 1] * rs * w[2 * p + 1];
        float r0 = (x0 * cs - x1 * sn) * sc;
        float r1 = (x0 * sn + x1 * cs) * sc;
        if (isq) {
            *(uint32_t*)(QF + (size_t)row * DIM + 2 * p) = packh(r0, r1);
        } else {
            uint32_t h = packh(r0, r1);
            __half2 H = *(__half2*)&h;
            uint32_t l = packh(r0 - __half2float(H.x), r1 - __half2float(H.y));
            *(uint32_t*)(KFH + (size_t)row * DIM + 2 * p) = h;
            *(uint32_t*)(KFL + (size_t)row * DIM + 2 * p) = l;
        }
    }
}

// ============== mma.sync flash attention (fp16 2-term, key-split) ==========
// 64 queries x 1 head per block, 8 warps = 4 row-groups x 2 key-halves.
// QK: S = Q*Kh + Q*Kl (Q single fp16).  PV: O += Ph*V + Pl*V (V single fp16).
// 2-stage ring of {Kh, Kl, V}; smem 70KB -> 2 CTAs/SM.
#define AQB  64
#define ASTR 136
#define AQR  (AQB * ASTR)          // 8704 elems (Q single)
#define ATL  (32 * ASTR)           // 4352 elems
#define ASTAGE (3 * ATL)           // Kh, Kl, V
#define ATT_SMEM_BYTES ((AQR + 2 * ASTAGE) * 2)   // 69632

__global__ __launch_bounds__(256, 2)
void attn_mma(const __half* __restrict__ Qf,
              const __half* __restrict__ Kfh, const __half* __restrict__ Kfl,
              const __half* __restrict__ Vf,
              __nv_bfloat16* __restrict__ Oh, __nv_bfloat16* __restrict__ Ol) {
    extern __shared__ __half smh[];
    const uint32_t sbase = s2u(smh);
    const int head = blockIdx.y;
    const int q0   = blockIdx.x * AQB;
    const int v    = q0 / VS;
    const int f    = (q0 % VS) / TPF;      // uniform: 64 | 448
    const int col0 = head * HD;
    const int tid  = threadIdx.x;
    const int warp = tid >> 5, lane = tid & 31;
    const int g    = warp >> 1;            // row group (0..3), 16 rows each
    const int h    = warp & 1;             // key half (0..1), 16 keys each

    // ---- load Q tile (single fp16) into smem ----
    for (int i = tid; i < AQB * 16; i += 256) {
        int r = i >> 4, seg = i & 15;
        *(uint4*)&smh[r * ASTR + seg * 8] =
            *(const uint4*)&Qf[(size_t)(q0 + r) * DIM + col0 + seg * 8];
    }

    const int baseA = v * VS;
    const int baseB = (1 - v) * VS + f * TPF;
    const int NT = 70;

    const __half* ptrs[3] = {Kfh, Kfl, Vf};

    auto issue_tile = [&](int t, int s) {
        int kb = (t < 56) ? (baseA + t * 32) : (baseB + (t - 56) * 32);
#pragma unroll
        for (int j = 0; j < 6; j++) {
            int i = tid + j * 256;        // 0..1535
            int arr = i >> 9;
            int idx = i & 511;
            int r = idx >> 4, seg = idx & 15;
            const __half* src = ptrs[arr] + (size_t)(kb + r) * DIM + col0 + seg * 8;
            uint32_t dst = sbase + (uint32_t)(AQR + s * ASTAGE + arr * ATL + r * ASTR + seg * 8) * 2;
            cp16(dst, src);
        }
        cp_commit();
    };

    issue_tile(0, 0);

    float m[2] = {-1e30f, -1e30f};
    float l[2] = {0.f, 0.f};
    float acc[16][4];
#pragma unroll
    for (int nt = 0; nt < 16; nt++)
#pragma unroll
        for (int j = 0; j < 4; j++) acc[nt][j] = 0.f;

    const uint32_t q_goff = (uint32_t)(g * 16 + (lane & 15)) * (ASTR * 2)
                          + (uint32_t)((lane >> 4) * 16);
    const uint32_t k_bro  = (uint32_t)(h * 16 + (lane & 7) + 8 * ((lane >> 4) & 1));
    const uint32_t k_bco  = (uint32_t)(((lane >> 3) & 1) * 16);
    const uint32_t v_row  = (uint32_t)(h * 16 + (lane & 15));
    const uint32_t v_cofs = (uint32_t)(8 * ((lane >> 4) & 1));

    for (int t = 0; t < NT; t++) {
        cp_wait<0>();
        __syncthreads();
        if (t + 1 < NT) issue_tile(t + 1, (t + 1) & 1);

        const uint32_t st = sbase + (uint32_t)(AQR + (t & 1) * ASTAGE) * 2;
        const uint32_t khb = st, klb = st + ATL * 2, vhb = st + 2 * ATL * 2;

        // ---- S = Q*Kh + Q*Kl  (two accumulator sets -> 4 indep chains) ----
        float Sa[2][4], Sb[2][4];
#pragma unroll
        for (int nt = 0; nt < 2; nt++)
#pragma unroll
            for (int j = 0; j < 4; j++) { Sa[nt][j] = 0.f; Sb[nt][j] = 0.f; }

#pragma unroll
        for (int ks = 0; ks < 8; ks++) {
            uint32_t aQ[4], bKh[4], bKl[4];
            ldsm_x4(aQ, sbase + q_goff + ks * 32);
            uint32_t boff = k_bro * (ASTR * 2) + ks * 32 + k_bco;
            ldsm_x4(bKh, khb + boff);
            ldsm_x4(bKl, klb + boff);
            mma16816h(Sa[0], aQ, &bKh[0]);
            mma16816h(Sa[1], aQ, &bKh[2]);
            mma16816h(Sb[0], aQ, &bKl[0]);
            mma16816h(Sb[1], aQ, &bKl[2]);
        }

        float S[2][4];
#pragma unroll
        for (int nt = 0; nt < 2; nt++)
#pragma unroll
            for (int j = 0; j < 4; j++) S[nt][j] = Sa[nt][j] + Sb[nt][j];

        // ---- online softmax over this warp's keys ----
        float mn[2], corr[2];
#pragma unroll
        for (int j = 0; j < 2; j++) {
            float mx = fmaxf(fmaxf(S[0][2 * j], S[0][2 * j + 1]),
                             fmaxf(S[1][2 * j], S[1][2 * j + 1]));
            mx = fmaxf(mx, __shfl_xor_sync(~0u, mx, 1));
            mx = fmaxf(mx, __shfl_xor_sync(~0u, mx, 2));
            mn[j] = fmaxf(m[j], mx);
            corr[j] = __expf(m[j] - mn[j]);
        }
        bool resc = !__all_sync(~0u, (mn[0] == m[0]) && (mn[1] == m[1]));
        m[0] = mn[0]; m[1] = mn[1];

        uint32_t ph[2][2], pl[2][2];
#pragma unroll
        for (int j = 0; j < 2; j++) {
            float rs = 0.f;
#pragma unroll
            for (int nt = 0; nt < 2; nt++) {
                float e0 = __expf(S[nt][2 * j]     - mn[j]);
                float e1 = __expf(S[nt][2 * j + 1] - mn[j]);
                S[nt][2 * j] = e0; S[nt][2 * j + 1] = e1;
                rs += e0 + e1;
            }
            rs += __shfl_xor_sync(~0u, rs, 1);
            rs += __shfl_xor_sync(~0u, rs, 2);
            l[j] = l[j] * corr[j] + rs;
        }
        if (resc) {
#pragma unroll
            for (int nt = 0; nt < 16; nt++) {
                acc[nt][0] *= corr[0]; acc[nt][1] *= corr[0];
                acc[nt][2] *= corr[1]; acc[nt][3] *= corr[1];
            }
        }
#pragma unroll
        for (int nt = 0; nt < 2; nt++) {
#pragma unroll
            for (int j = 0; j < 2; j++) {
                float e0 = S[nt][2 * j], e1 = S[nt][2 * j + 1];
                uint32_t hh = packh(e0, e1);
                __half2 H = *(__half2*)&hh;
                ph[nt][j] = hh;
                pl[nt][j] = packh(e0 - __half2float(H.x), e1 - __half2float(H.y));
            }
        }

        // ---- out += (Ph + Pl) * V over this warp's keys ----
        uint32_t aPh[4] = {ph[0][0], ph[0][1], ph[1][0], ph[1][1]};
        uint32_t aPl[4] = {pl[0][0], pl[0][1], pl[1][0], pl[1][1]};
#pragma unroll
        for (int dp = 0; dp < 8; dp++) {
            uint32_t bV[4];
            uint32_t voff = v_row * (ASTR * 2) + (uint32_t)(dp * 16 + v_cofs) * 2;
            ldsm_x4_t(bV, vhb + voff);
            mma16816h(acc[2 * dp],     aPh, &bV[0]);
            mma16816h(acc[2 * dp + 1], aPh, &bV[2]);
            mma16816h(acc[2 * dp],     aPl, &bV[0]);
            mma16816h(acc[2 * dp + 1], aPl, &bV[2]);
        }
    }

    // ---- merge warp pairs (h=1 publishes, h=0 combines) ----
    __syncthreads();
    float* ex = (float*)smh;   // 4 groups x 32 lanes x 68 floats = 34816 B
    if (h == 1) {
        float* d = ex + (g * 32 + lane) * 68;
        d[0] = m[0]; d[1] = m[1]; d[2] = l[0]; d[3] = l[1];
#pragma unroll
        for (int nt = 0; nt < 16; nt++) {
            d[4 + 4 * nt + 0] = acc[nt][0];
            d[4 + 4 * nt + 1] = acc[nt][1];
            d[4 + 4 * nt + 2] = acc[nt][2];
            d[4 + 4 * nt + 3] = acc[nt][3];
        }
    }
    __syncthreads();
    if (h == 0) {
        const float* d = ex + (g * 32 + lane) * 68;
        float pm[2] = {d[0], d[1]};
        float pll[2] = {d[2], d[3]};
        float a[2], b[2], inv[2];
#pragma unroll
        for (int j = 0; j < 2; j++) {
            float M = fmaxf(m[j], pm[j]);
            a[j] = __expf(m[j] - M);
            b[j] = __expf(pm[j] - M);
            inv[j] = 1.f / (a[j] * l[j] + b[j] * pll[j]);
        }
#pragma unroll
        for (int j = 0; j < 2; j++) {
            int row = q0 + g * 16 + (lane >> 2) + 8 * j;
#pragma unroll
            for (int nt = 0; nt < 16; nt++) {
                float o0 = (a[j] * acc[nt][2 * j]     + b[j] * d[4 + 4 * nt + 2 * j])     * inv[j];
                float o1 = (a[j] * acc[nt][2 * j + 1] + b[j] * d[4 + 4 * nt + 2 * j + 1]) * inv[j];
                uint32_t hh = packbf(o0, o1);
                __nv_bfloat162 H = *(__nv_bfloat162*)&hh;
                uint32_t lo = packbf(o0 - __bfloat162float(H.x), o1 - __bfloat162float(H.y));
                size_t off = (size_t)row * DIM + col0 + nt * 8 + 2 * (lane & 3);
                *(uint32_t*)(Oh + off) = hh;
                *(uint32_t*)(Ol + off) = lo;
            }
        }
    }
}

// ======================= launch =======================
extern "C" void kernel_launch(void* const* d_in, const int* in_sizes, int n_in,
                              void* d_out, int out_size) {
    const float* x     = (const float*)d_in[0];
    const float* freqs = (const float*)d_in[1];
    const float* q_w   = (const float*)d_in[2];
    const float* q_b   = (const float*)d_in[3];
    const float* k_w   = (const float*)d_in[4];
    const float* k_b   = (const float*)d_in[5];
    const float* v_w   = (const float*)d_in[6];
    const float* v_b   = (const float*)d_in[7];
    const float* o_w   = (const float*)d_in[8];
    const float* o_b   = (const float*)d_in[9];
    const float* nqw   = (const float*)d_in[10];
    const float* nkw   = (const float*)d_in[11];

    float *gq, *gk;
    __nv_bfloat16 *xh, *xl, *oh, *ol, *wh, *wl;
    __half *qf, *kfh, *kfl, *vf;
    cudaGetSymbolAddress((void**)&gq, g_q);
    cudaGetSymbolAddress((void**)&gk, g_k);
    cudaGetSymbolAddress((void**)&xh, g_xh);
    cudaGetSymbolAddress((void**)&xl, g_xl);
    cudaGetSymbolAddress((void**)&qf, g_qf);
    cudaGetSymbolAddress((void**)&kfh, g_kfh);
    cudaGetSymbolAddress((void**)&kfl, g_kfl);
    cudaGetSymbolAddress((void**)&vf, g_vf);
    cudaGetSymbolAddress((void**)&oh, g_oh);
    cudaGetSymbolAddress((void**)&ol, g_ol);
    cudaGetSymbolAddress((void**)&wh, g_wh);
    cudaGetSymbolAddress((void**)&wl, g_wl);

    const size_t WSZ = (size_t)DIM * DIM;
    __nv_bfloat16 *owh = wh + 3 * WSZ, *owl = wl + 3 * WSZ;

    split_all<<<dim3((NX4 + 255) / 256, 5), 256>>>(x, q_w, k_w, v_w, o_w, xh, xl, wh, wl);

    cudaFuncSetAttribute(gemm_qkv, cudaFuncAttributeMaxDynamicSharedMemorySize,
                         GEMM_SMEM_BYTES);
    cudaFuncSetAttribute(gemm_o, cudaFuncAttributeMaxDynamicSharedMemorySize,
                         GEMM_SMEM_BYTES);
    gemm_qkv<<<dim3(DIM / 128, TS / 128, 3), 256, GEMM_SMEM_BYTES>>>(
        xh, xl, wh, wl, q_b, k_b, v_b, gq, gk, vf);

    norm_rope_kernel<<<dim3(TS, 2), 256>>>(gq, gk, freqs, nqw, nkw, qf, kfh, kfl);

    cudaFuncSetAttribute(attn_mma, cudaFuncAttributeMaxDynamicSharedMemorySize,
                         ATT_SMEM_BYTES);
    attn_mma<<<dim3(TS / AQB, NH), 256, ATT_SMEM_BYTES>>>(qf, kfh, kfl, vf, oh, ol);

    gemm_o<<<dim3(DIM / 128, TS / 128), 256, GEMM_SMEM_BYTES>>>(
        oh, ol, owh, owl, o_b, (float*)d_out);
}

// round 14
// speedup vs baseline: 1.3954x; 1.1993x over previous
#include <cuda_runtime.h>
#include <cuda_bf16.h>
#include <cuda_fp16.h>
#include <cstdint>

#define TS   3584
#define DIM  1536
#define NH   12
#define HD   128
#define VS   1792
#define TPF  448
#define NW   28
#define EPS  1e-6f
#define SCALE 0.08838834764831845f   // 1/sqrt(128)

// -------- scratch (device globals; no allocations allowed) --------
__device__ float g_q[(size_t)TS * DIM];
__device__ float g_k[(size_t)TS * DIM];
__device__ __half g_xf[(size_t)TS * DIM];     // X single fp16
__device__ __half g_qf[(size_t)TS * DIM];     // Q single fp16 (pre-scaled)
__device__ __half g_kfh[(size_t)TS * DIM];    // K fp16 hi
__device__ __half g_kfl[(size_t)TS * DIM];    // K fp16 lo
__device__ __half g_vf[(size_t)TS * DIM];     // V single fp16
__device__ __half g_of[(size_t)TS * DIM];     // attention out, single fp16
__device__ __half g_wfh[4][(size_t)DIM * DIM]; // weights fp16 hi
__device__ __half g_wfl[4][(size_t)DIM * DIM]; // weights fp16 lo

// ======================= PTX helpers =======================
__device__ __forceinline__ uint32_t s2u(const void* p) {
    uint32_t a;
    asm("{ .reg .u64 t; cvta.to.shared.u64 t, %1; cvt.u32.u64 %0, t; }"
        : "=r"(a) : "l"(p));
    return a;
}
__device__ __forceinline__ void ldsm_x4(uint32_t* r, uint32_t addr) {
    asm volatile("ldmatrix.sync.aligned.m8n8.x4.shared.b16 {%0,%1,%2,%3}, [%4];"
                 : "=r"(r[0]), "=r"(r[1]), "=r"(r[2]), "=r"(r[3]) : "r"(addr));
}
__device__ __forceinline__ void ldsm_x4_t(uint32_t* r, uint32_t addr) {
    asm volatile("ldmatrix.sync.aligned.m8n8.x4.trans.shared.b16 {%0,%1,%2,%3}, [%4];"
                 : "=r"(r[0]), "=r"(r[1]), "=r"(r[2]), "=r"(r[3]) : "r"(addr));
}
__device__ __forceinline__ void mma16816h(float* c, const uint32_t* a, const uint32_t* b) {
    asm volatile(
        "mma.sync.aligned.m16n8k16.row.col.f32.f16.f16.f32 "
        "{%0,%1,%2,%3}, {%4,%5,%6,%7}, {%8,%9}, {%0,%1,%2,%3};"
        : "+f"(c[0]), "+f"(c[1]), "+f"(c[2]), "+f"(c[3])
        : "r"(a[0]), "r"(a[1]), "r"(a[2]), "r"(a[3]), "r"(b[0]), "r"(b[1]));
}
__device__ __forceinline__ void cp16(uint32_t dst, const void* src) {
    asm volatile("cp.async.ca.shared.global [%0], [%1], 16;"
                 :: "r"(dst), "l"(src) : "memory");
}
__device__ __forceinline__ void cp_commit() {
    asm volatile("cp.async.commit_group;" ::: "memory");
}
template <int N>
__device__ __forceinline__ void cp_wait() {
    asm volatile("cp.async.wait_group %0;" :: "n"(N) : "memory");
}
__device__ __forceinline__ uint32_t packh(float a, float b) {
    __half2 h = __floats2half2_rn(a, b);
    return *(uint32_t*)&h;
}

// ======================= fp32 -> fp16 splits (fused) ========================
#define NX4 (TS * DIM / 4)
#define NW4 (DIM * DIM / 4)

__global__ __launch_bounds__(256)
void split_all(const float* __restrict__ x,
               const float* __restrict__ qw, const float* __restrict__ kw,
               const float* __restrict__ vw, const float* __restrict__ ow,
               __half* __restrict__ xf,
               __half* __restrict__ wfh, __half* __restrict__ wfl) {
    int i = blockIdx.x * 256 + threadIdx.x;
    int z = blockIdx.y;
    if (z == 0) {
        if (i >= NX4) return;
        float4 v = ((const float4*)x)[i];
        *(uint32_t*)(xf + 4 * (size_t)i)     = packh(v.x, v.y);
        *(uint32_t*)(xf + 4 * (size_t)i + 2) = packh(v.z, v.w);
    } else {
        if (i >= NW4) return;
        const float* in = (z == 1) ? qw : (z == 2) ? kw : (z == 3) ? vw : ow;
        float4 v = ((const float4*)in)[i];
        __half h0 = __float2half_rn(v.x), h1 = __float2half_rn(v.y);
        __half h2 = __float2half_rn(v.z), h3 = __float2half_rn(v.w);
        __half2 H0; H0.x = h0; H0.y = h1;
        __half2 H1; H1.x = h2; H1.y = h3;
        uint32_t l0 = packh(v.x - __half2float(h0), v.y - __half2float(h1));
        uint32_t l1 = packh(v.z - __half2float(h2), v.w - __half2float(h3));
        size_t base = (size_t)(z - 1) * DIM * DIM + 4 * (size_t)i;
        *(uint32_t*)(wfh + base)     = *(uint32_t*)&H0;
        *(uint32_t*)(wfh + base + 2) = *(uint32_t*)&H1;
        *(uint32_t*)(wfl + base)     = l0;
        *(uint32_t*)(wfl + base + 2) = l1;
    }
}

// ======================= mma.sync fp16 2-term GEMM core =====================
// C = A @ (Wh + Wl)^T + bias; A single fp16. 256 threads, 8 warps (2M x 4N),
// 2-stage cp.async ring of {A, Wh, Wl}; 60KB smem -> 2 CTAs/SM.
#define SSTR 40
#define TILE_E (128 * SSTR)
#define TILE_B (TILE_E * 2)
#define GSTAGE_E (3 * TILE_E)
#define GEMM_SMEM_BYTES (2 * GSTAGE_E * 2)   // 61440

struct GemmOut {
    float acc[4][4][4];
};

__device__ __forceinline__ void gemm_core_h(
    const __half* __restrict__ A,
    const __half* __restrict__ Wh, const __half* __restrict__ Wl,
    int m0, int n0, int K, __half* sm, GemmOut& out) {
    const int tid  = threadIdx.x;
    const int warp = tid >> 5, lane = tid & 31;
    const int wm   = warp & 1;
    const int wn   = warp >> 1;
    const uint32_t sbase = s2u(sm);

#pragma unroll
    for (int i = 0; i < 4; i++)
#pragma unroll
        for (int j = 0; j < 4; j++)
#pragma unroll
            for (int k = 0; k < 4; k++) out.acc[i][j][k] = 0.f;

    const __half* srcs[3] = {A, Wh, Wl};

    auto issue_chunk = [&](int c, int s) {
#pragma unroll
        for (int j = 0; j < 6; j++) {
            int i = tid + j * 256;            // 0..1535
            int arr = i >> 9;
            int idx = i & 511;
            int row = idx >> 2, seg = idx & 3;
            const __half* src = srcs[arr] +
                (size_t)((arr == 0 ? m0 : n0) + row) * K + c * 32 + seg * 8;
            uint32_t dst = sbase + (uint32_t)(s * GSTAGE_E + arr * TILE_E + row * SSTR + seg * 8) * 2;
            cp16(dst, src);
        }
        cp_commit();
    };

    const int NC = K / 32;
    issue_chunk(0, 0);

    const uint32_t arow = (uint32_t)(wm * 64 + (lane & 15));
    const uint32_t acol = (uint32_t)((lane >> 4) * 16);
    const uint32_t bro  = (uint32_t)((lane & 7) + 8 * ((lane >> 4) & 1));
    const uint32_t bco  = (uint32_t)(((lane >> 3) & 1) * 16);

    for (int c = 0; c < NC; c++) {
        cp_wait<0>();
        __syncthreads();
        if (c + 1 < NC) issue_chunk(c + 1, (c + 1) & 1);
        const uint32_t bb = sbase + (uint32_t)((c & 1) * GSTAGE_E) * 2;
#pragma unroll
        for (int ks = 0; ks < 2; ks++) {
            uint32_t aF[4][4], bH[8], bL[8];
            const uint32_t aoff = arow * (SSTR * 2) + ks * 32 + acol;
#pragma unroll
            for (int mt = 0; mt < 4; mt++)
                ldsm_x4(aF[mt], bb + 0 * TILE_B + aoff + mt * 16 * (SSTR * 2));
#pragma unroll
            for (int p = 0; p < 2; p++) {
                uint32_t boff = (uint32_t)(wn * 32 + p * 16 + bro) * (SSTR * 2) + ks * 32 + bco;
                ldsm_x4(&bH[4 * p], bb + 1 * TILE_B + boff);
            }
#pragma unroll
            for (int mt = 0; mt < 4; mt++)
#pragma unroll
                for (int nt = 0; nt < 4; nt++)
                    mma16816h(out.acc[mt][nt], aF[mt], &bH[2 * nt]);
#pragma unroll
            for (int p = 0; p < 2; p++) {
                uint32_t boff = (uint32_t)(wn * 32 + p * 16 + bro) * (SSTR * 2) + ks * 32 + bco;
                ldsm_x4(&bL[4 * p], bb + 2 * TILE_B + boff);
            }
#pragma unroll
            for (int mt = 0; mt < 4; mt++)
#pragma unroll
                for (int nt = 0; nt < 4; nt++)
                    mma16816h(out.acc[mt][nt], aF[mt], &bL[2 * nt]);
        }
    }
}

// ---- fused QKV projection: z = 0 (Q, f32) / 1 (K, f32) / 2 (V, fp16) ----
__global__ __launch_bounds__(256, 2)
void gemm_qkv(const __half* __restrict__ xf,
              const __half* __restrict__ wfh, const __half* __restrict__ wfl,
              const float* __restrict__ qb, const float* __restrict__ kb,
              const float* __restrict__ vb,
              float* __restrict__ gq, float* __restrict__ gk,
              __half* __restrict__ vf) {
    extern __shared__ __half smg[];
    const int z  = blockIdx.z;
    const int m0 = blockIdx.y * 128, n0 = blockIdx.x * 128;
    const size_t WSZ = (size_t)DIM * DIM;
    const float* bias = (z == 0) ? qb : (z == 1) ? kb : vb;

    GemmOut out;
    gemm_core_h(xf, wfh + (size_t)z * WSZ, wfl + (size_t)z * WSZ,
                m0, n0, DIM, smg, out);

    const int warp = threadIdx.x >> 5, lane = threadIdx.x & 31;
    const int row_base = m0 + (warp & 1) * 64 + (lane >> 2);
    const int col_base = n0 + (warp >> 1) * 32 + (lane & 3) * 2;
    float* Cf = (z == 0) ? gq : gk;
#pragma unroll
    for (int mt = 0; mt < 4; mt++) {
#pragma unroll
        for (int nt = 0; nt < 4; nt++) {
            int r = row_base + mt * 16;
            int cc = col_base + nt * 8;
            float bx = bias[cc], by = bias[cc + 1];
            float v00 = out.acc[mt][nt][0] + bx, v01 = out.acc[mt][nt][1] + by;
            float v10 = out.acc[mt][nt][2] + bx, v11 = out.acc[mt][nt][3] + by;
            if (z < 2) {
                *(float2*)(Cf + (size_t)r * DIM + cc)       = make_float2(v00, v01);
                *(float2*)(Cf + (size_t)(r + 8) * DIM + cc) = make_float2(v10, v11);
            } else {
                *(uint32_t*)(vf + (size_t)r * DIM + cc)       = packh(v00, v01);
                *(uint32_t*)(vf + (size_t)(r + 8) * DIM + cc) = packh(v10, v11);
            }
        }
    }
}

// ---- O projection (f32 out) ----
__global__ __launch_bounds__(256, 2)
void gemm_o(const __half* __restrict__ A,
            const __half* __restrict__ Wh, const __half* __restrict__ Wl,
            const float* __restrict__ bias, float* __restrict__ Cf) {
    extern __shared__ __half smg[];
    const int m0 = blockIdx.y * 128, n0 = blockIdx.x * 128;
    GemmOut out;
    gemm_core_h(A, Wh, Wl, m0, n0, DIM, smg, out);

    const int warp = threadIdx.x >> 5, lane = threadIdx.x & 31;
    const int row_base = m0 + (warp & 1) * 64 + (lane >> 2);
    const int col_base = n0 + (warp >> 1) * 32 + (lane & 3) * 2;
#pragma unroll
    for (int mt = 0; mt < 4; mt++) {
#pragma unroll
        for (int nt = 0; nt < 4; nt++) {
            int r = row_base + mt * 16;
            int cc = col_base + nt * 8;
            float bx = bias[cc], by = bias[cc + 1];
            *(float2*)(Cf + (size_t)r * DIM + cc) =
                make_float2(out.acc[mt][nt][0] + bx, out.acc[mt][nt][1] + by);
            *(float2*)(Cf + (size_t)(r + 8) * DIM + cc) =
                make_float2(out.acc[mt][nt][2] + bx, out.acc[mt][nt][3] + by);
        }
    }
}

// ======================= RMSNorm + RoPE =======================
// Q -> single fp16 (pre-scaled by SCALE).  K -> fp16 hi/lo.
__global__ __launch_bounds__(256)
void norm_rope_kernel(const float* __restrict__ q, const float* __restrict__ k,
                      const float* __restrict__ freqs,
                      const float* __restrict__ nqw, const float* __restrict__ nkw,
                      __half* __restrict__ QF,
                      __half* __restrict__ KFH, __half* __restrict__ KFL) {
    const int row = blockIdx.x;
    const int isq = (blockIdx.y == 0);
    const float* x = (isq ? q : k) + (size_t)row * DIM;
    const float* w = isq ? nqw : nkw;
    const float sc = isq ? SCALE : 1.f;
    const int tid = threadIdx.x;

    float ss = 0.f;
    for (int i = tid; i < DIM; i += 256) { float v = x[i]; ss += v * v; }
#pragma unroll
    for (int o = 16; o > 0; o >>= 1) ss += __shfl_xor_sync(~0u, ss, o);
    __shared__ float warpsum[8];
    if ((tid & 31) == 0) warpsum[tid >> 5] = ss;
    __syncthreads();
    float tot = 0.f;
#pragma unroll
    for (int i = 0; i < 8; i++) tot += warpsum[i];
    const float rs = rsqrtf(tot / (float)DIM + EPS);

    const int tv = row % VS;
    const int f  = tv / TPF;
    const int r  = tv % TPF;
    const int hh = r / NW;
    const int ww = r % NW;

    for (int p = tid; p < DIM / 2; p += 256) {
        int c = p & 63;
        int idx = (c < 22) ? f : ((c < 43) ? hh : ww);
        float ang = freqs[idx * 64 + c];
        float sn, cs;
        sincosf(ang, &sn, &cs);
        float x0 = x[2 * p]     * rs * w[2 * p];
        float x1 = x[2 * p + 1] * rs * w[2 * p + 1];
        float r0 = (x0 * cs - x1 * sn) * sc;
        float r1 = (x0 * sn + x1 * cs) * sc;
        if (isq) {
            *(uint32_t*)(QF + (size_t)row * DIM + 2 * p) = packh(r0, r1);
        } else {
            uint32_t h = packh(r0, r1);
            __half2 H = *(__half2*)&h;
            uint32_t l = packh(r0 - __half2float(H.x), r1 - __half2float(H.y));
            *(uint32_t*)(KFH + (size_t)row * DIM + 2 * p) = h;
            *(uint32_t*)(KFL + (size_t)row * DIM + 2 * p) = l;
        }
    }
}

// ============== mma.sync flash attention (fp16 2-term, key-split) ==========
// 64 queries x 1 head per block, 8 warps = 4 row-groups x 2 key-halves.
// QK: S = Q*Kh + Q*Kl.  PV: O += Ph*V + Pl*V.  Output: single fp16.
#define AQB  64
#define ASTR 136
#define AQR  (AQB * ASTR)
#define ATL  (32 * ASTR)
#define ASTAGE (3 * ATL)
#define ATT_SMEM_BYTES ((AQR + 2 * ASTAGE) * 2)   // 69632

__global__ __launch_bounds__(256, 2)
void attn_mma(const __half* __restrict__ Qf,
              const __half* __restrict__ Kfh, const __half* __restrict__ Kfl,
              const __half* __restrict__ Vf,
              __half* __restrict__ Of) {
    extern __shared__ __half smh[];
    const uint32_t sbase = s2u(smh);
    const int head = blockIdx.y;
    const int q0   = blockIdx.x * AQB;
    const int v    = q0 / VS;
    const int f    = (q0 % VS) / TPF;
    const int col0 = head * HD;
    const int tid  = threadIdx.x;
    const int warp = tid >> 5, lane = tid & 31;
    const int g    = warp >> 1;
    const int h    = warp & 1;

    for (int i = tid; i < AQB * 16; i += 256) {
        int r = i >> 4, seg = i & 15;
        *(uint4*)&smh[r * ASTR + seg * 8] =
            *(const uint4*)&Qf[(size_t)(q0 + r) * DIM + col0 + seg * 8];
    }

    const int baseA = v * VS;
    const int baseB = (1 - v) * VS + f * TPF;
    const int NT = 70;

    const __half* ptrs[3] = {Kfh, Kfl, Vf};

    auto issue_tile = [&](int t, int s) {
        int kb = (t < 56) ? (baseA + t * 32) : (baseB + (t - 56) * 32);
#pragma unroll
        for (int j = 0; j < 6; j++) {
            int i = tid + j * 256;
            int arr = i >> 9;
            int idx = i & 511;
            int r = idx >> 4, seg = idx & 15;
            const __half* src = ptrs[arr] + (size_t)(kb + r) * DIM + col0 + seg * 8;
            uint32_t dst = sbase + (uint32_t)(AQR + s * ASTAGE + arr * ATL + r * ASTR + seg * 8) * 2;
            cp16(dst, src);
        }
        cp_commit();
    };

    issue_tile(0, 0);

    float m[2] = {-1e30f, -1e30f};
    float l[2] = {0.f, 0.f};
    float acc[16][4];
#pragma unroll
    for (int nt = 0; nt < 16; nt++)
#pragma unroll
        for (int j = 0; j < 4; j++) acc[nt][j] = 0.f;

    const uint32_t q_goff = (uint32_t)(g * 16 + (lane & 15)) * (ASTR * 2)
                          + (uint32_t)((lane >> 4) * 16);
    const uint32_t k_bro  = (uint32_t)(h * 16 + (lane & 7) + 8 * ((lane >> 4) & 1));
    const uint32_t k_bco  = (uint32_t)(((lane >> 3) & 1) * 16);
    const uint32_t v_row  = (uint32_t)(h * 16 + (lane & 15));
    const uint32_t v_cofs = (uint32_t)(8 * ((lane >> 4) & 1));

    for (int t = 0; t < NT; t++) {
        cp_wait<0>();
        __syncthreads();
        if (t + 1 < NT) issue_tile(t + 1, (t + 1) & 1);

        const uint32_t st = sbase + (uint32_t)(AQR + (t & 1) * ASTAGE) * 2;
        const uint32_t khb = st, klb = st + ATL * 2, vhb = st + 2 * ATL * 2;

        float Sa[2][4], Sb[2][4];
#pragma unroll
        for (int nt = 0; nt < 2; nt++)
#pragma unroll
            for (int j = 0; j < 4; j++) { Sa[nt][j] = 0.f; Sb[nt][j] = 0.f; }

#pragma unroll
        for (int ks = 0; ks < 8; ks++) {
            uint32_t aQ[4], bKh[4], bKl[4];
            ldsm_x4(aQ, sbase + q_goff + ks * 32);
            uint32_t boff = k_bro * (ASTR * 2) + ks * 32 + k_bco;
            ldsm_x4(bKh, khb + boff);
            ldsm_x4(bKl, klb + boff);
            mma16816h(Sa[0], aQ, &bKh[0]);
            mma16816h(Sa[1], aQ, &bKh[2]);
            mma16816h(Sb[0], aQ, &bKl[0]);
            mma16816h(Sb[1], aQ, &bKl[2]);
        }

        float S[2][4];
#pragma unroll
        for (int nt = 0; nt < 2; nt++)
#pragma unroll
            for (int j = 0; j < 4; j++) S[nt][j] = Sa[nt][j] + Sb[nt][j];

        float mn[2], corr[2];
#pragma unroll
        for (int j = 0; j < 2; j++) {
            float mx = fmaxf(fmaxf(S[0][2 * j], S[0][2 * j + 1]),
                             fmaxf(S[1][2 * j], S[1][2 * j + 1]));
            mx = fmaxf(mx, __shfl_xor_sync(~0u, mx, 1));
            mx = fmaxf(mx, __shfl_xor_sync(~0u, mx, 2));
            mn[j] = fmaxf(m[j], mx);
            corr[j] = __expf(m[j] - mn[j]);
        }
        bool resc = !__all_sync(~0u, (mn[0] == m[0]) && (mn[1] == m[1]));
        m[0] = mn[0]; m[1] = mn[1];

        uint32_t ph[2][2], pl[2][2];
#pragma unroll
        for (int j = 0; j < 2; j++) {
            float rs = 0.f;
#pragma unroll
            for (int nt = 0; nt < 2; nt++) {
                float e0 = __expf(S[nt][2 * j]     - mn[j]);
                float e1 = __expf(S[nt][2 * j + 1] - mn[j]);
                S[nt][2 * j] = e0; S[nt][2 * j + 1] = e1;
                rs += e0 + e1;
            }
            rs += __shfl_xor_sync(~0u, rs, 1);
            rs += __shfl_xor_sync(~0u, rs, 2);
            l[j] = l[j] * corr[j] + rs;
        }
        if (resc) {
#pragma unroll
            for (int nt = 0; nt < 16; nt++) {
                acc[nt][0] *= corr[0]; acc[nt][1] *= corr[0];
                acc[nt][2] *= corr[1]; acc[nt][3] *= corr[1];
            }
        }
#pragma unroll
        for (int nt = 0; nt < 2; nt++) {
#pragma unroll
            for (int j = 0; j < 2; j++) {
                float e0 = S[nt][2 * j], e1 = S[nt][2 * j + 1];
                uint32_t hh = packh(e0, e1);
                __half2 H = *(__half2*)&hh;
                ph[nt][j] = hh;
                pl[nt][j] = packh(e0 - __half2float(H.x), e1 - __half2float(H.y));
            }
        }

        uint32_t aPh[4] = {ph[0][0], ph[0][1], ph[1][0], ph[1][1]};
        uint32_t aPl[4] = {pl[0][0], pl[0][1], pl[1][0], pl[1][1]};
#pragma unroll
        for (int dp = 0; dp < 8; dp++) {
            uint32_t bV[4];
            uint32_t voff = v_row * (ASTR * 2) + (uint32_t)(dp * 16 + v_cofs) * 2;
            ldsm_x4_t(bV, vhb + voff);
            mma16816h(acc[2 * dp],     aPh, &bV[0]);
            mma16816h(acc[2 * dp + 1], aPh, &bV[2]);
            mma16816h(acc[2 * dp],     aPl, &bV[0]);
            mma16816h(acc[2 * dp + 1], aPl, &bV[2]);
        }
    }

    // ---- merge warp pairs (h=1 publishes, h=0 combines) ----
    __syncthreads();
    float* ex = (float*)smh;
    if (h == 1) {
        float* d = ex + (g * 32 + lane) * 68;
        d[0] = m[0]; d[1] = m[1]; d[2] = l[0]; d[3] = l[1];
#pragma unroll
        for (int nt = 0; nt < 16; nt++) {
            d[4 + 4 * nt + 0] = acc[nt][0];
            d[4 + 4 * nt + 1] = acc[nt][1];
            d[4 + 4 * nt + 2] = acc[nt][2];
            d[4 + 4 * nt + 3] = acc[nt][3];
        }
    }
    __syncthreads();
    if (h == 0) {
        const float* d = ex + (g * 32 + lane) * 68;
        float pm[2] = {d[0], d[1]};
        float pll[2] = {d[2], d[3]};
        float a[2], b[2], inv[2];
#pragma unroll
        for (int j = 0; j < 2; j++) {
            float M = fmaxf(m[j], pm[j]);
            a[j] = __expf(m[j] - M);
            b[j] = __expf(pm[j] - M);
            inv[j] = 1.f / (a[j] * l[j] + b[j] * pll[j]);
        }
#pragma unroll
        for (int j = 0; j < 2; j++) {
            int row = q0 + g * 16 + (lane >> 2) + 8 * j;
#pragma unroll
            for (int nt = 0; nt < 16; nt++) {
                float o0 = (a[j] * acc[nt][2 * j]     + b[j] * d[4 + 4 * nt + 2 * j])     * inv[j];
                float o1 = (a[j] * acc[nt][2 * j + 1] + b[j] * d[4 + 4 * nt + 2 * j + 1]) * inv[j];
                size_t off = (size_t)row * DIM + col0 + nt * 8 + 2 * (lane & 3);
                *(uint32_t*)(Of + off) = packh(o0, o1);
            }
        }
    }
}

// ======================= launch =======================
extern "C" void kernel_launch(void* const* d_in, const int* in_sizes, int n_in,
                              void* d_out, int out_size) {
    const float* x     = (const float*)d_in[0];
    const float* freqs = (const float*)d_in[1];
    const float* q_w   = (const float*)d_in[2];
    const float* q_b   = (const float*)d_in[3];
    const float* k_w   = (const float*)d_in[4];
    const float* k_b   = (const float*)d_in[5];
    const float* v_w   = (const float*)d_in[6];
    const float* v_b   = (const float*)d_in[7];
    const float* o_w   = (const float*)d_in[8];
    const float* o_b   = (const float*)d_in[9];
    const float* nqw   = (const float*)d_in[10];
    const float* nkw   = (const float*)d_in[11];

    float *gq, *gk;
    __half *xf, *qf, *kfh, *kfl, *vf, *of, *wfh, *wfl;
    cudaGetSymbolAddress((void**)&gq, g_q);
    cudaGetSymbolAddress((void**)&gk, g_k);
    cudaGetSymbolAddress((void**)&xf, g_xf);
    cudaGetSymbolAddress((void**)&qf, g_qf);
    cudaGetSymbolAddress((void**)&kfh, g_kfh);
    cudaGetSymbolAddress((void**)&kfl, g_kfl);
    cudaGetSymbolAddress((void**)&vf, g_vf);
    cudaGetSymbolAddress((void**)&of, g_of);
    cudaGetSymbolAddress((void**)&wfh, g_wfh);
    cudaGetSymbolAddress((void**)&wfl, g_wfl);

    const size_t WSZ = (size_t)DIM * DIM;
    __half *owfh = wfh + 3 * WSZ, *owfl = wfl + 3 * WSZ;

    split_all<<<dim3((NX4 + 255) / 256, 5), 256>>>(x, q_w, k_w, v_w, o_w, xf, wfh, wfl);

    cudaFuncSetAttribute(gemm_qkv, cudaFuncAttributeMaxDynamicSharedMemorySize,
                         GEMM_SMEM_BYTES);
    cudaFuncSetAttribute(gemm_o, cudaFuncAttributeMaxDynamicSharedMemorySize,
                         GEMM_SMEM_BYTES);
    gemm_qkv<<<dim3(DIM / 128, TS / 128, 3), 256, GEMM_SMEM_BYTES>>>(
        xf, wfh, wfl, q_b, k_b, v_b, gq, gk, vf);

    norm_rope_kernel<<<dim3(TS, 2), 256>>>(gq, gk, freqs, nqw, nkw, qf, kfh, kfl);

    cudaFuncSetAttribute(attn_mma, cudaFuncAttributeMaxDynamicSharedMemorySize,
                         ATT_SMEM_BYTES);
    attn_mma<<<dim3(TS / AQB, NH), 256, ATT_SMEM_BYTES>>>(qf, kfh, kfl, vf, of);

    gemm_o<<<dim3(DIM / 128, TS / 128), 256, GEMM_SMEM_BYTES>>>(
        of, owfh, owfl, o_b, (float*)d_out);
}

// round 15
// speedup vs baseline: 1.4713x; 1.0544x over previous
#include <cuda_runtime.h>
#include <cuda_bf16.h>
#include <cuda_fp16.h>
#include <cstdint>

#define TS   3584
#define DIM  1536
#define NH   12
#define HD   128
#define VS   1792
#define TPF  448
#define NW   28
#define EPS  1e-6f
#define SCALE 0.08838834764831845f   // 1/sqrt(128)

// -------- scratch (device globals; no allocations allowed) --------
__device__ float g_q[(size_t)TS * DIM];
__device__ float g_k[(size_t)TS * DIM];
__device__ __half g_xf[(size_t)TS * DIM];     // X single fp16
__device__ __half g_qf[(size_t)TS * DIM];     // Q single fp16 (pre-scaled)
__device__ __half g_kfh[(size_t)TS * DIM];    // K fp16 hi
__device__ __half g_kfl[(size_t)TS * DIM];    // K fp16 lo
__device__ __half g_vf[(size_t)TS * DIM];     // V single fp16
__device__ __half g_of[(size_t)TS * DIM];     // attention out, single fp16
__device__ __half g_wfh[4][(size_t)DIM * DIM]; // weights fp16 hi
__device__ __half g_wfl[4][(size_t)DIM * DIM]; // weights fp16 lo

// ======================= PTX helpers =======================
__device__ __forceinline__ uint32_t s2u(const void* p) {
    uint32_t a;
    asm("{ .reg .u64 t; cvta.to.shared.u64 t, %1; cvt.u32.u64 %0, t; }"
        : "=r"(a) : "l"(p));
    return a;
}
__device__ __forceinline__ void ldsm_x4(uint32_t* r, uint32_t addr) {
    asm volatile("ldmatrix.sync.aligned.m8n8.x4.shared.b16 {%0,%1,%2,%3}, [%4];"
                 : "=r"(r[0]), "=r"(r[1]), "=r"(r[2]), "=r"(r[3]) : "r"(addr));
}
__device__ __forceinline__ void ldsm_x4_t(uint32_t* r, uint32_t addr) {
    asm volatile("ldmatrix.sync.aligned.m8n8.x4.trans.shared.b16 {%0,%1,%2,%3}, [%4];"
                 : "=r"(r[0]), "=r"(r[1]), "=r"(r[2]), "=r"(r[3]) : "r"(addr));
}
__device__ __forceinline__ void mma16816h(float* c, const uint32_t* a, const uint32_t* b) {
    asm volatile(
        "mma.sync.aligned.m16n8k16.row.col.f32.f16.f16.f32 "
        "{%0,%1,%2,%3}, {%4,%5,%6,%7}, {%8,%9}, {%0,%1,%2,%3};"
        : "+f"(c[0]), "+f"(c[1]), "+f"(c[2]), "+f"(c[3])
        : "r"(a[0]), "r"(a[1]), "r"(a[2]), "r"(a[3]), "r"(b[0]), "r"(b[1]));
}
__device__ __forceinline__ void cp16(uint32_t dst, const void* src) {
    asm volatile("cp.async.ca.shared.global [%0], [%1], 16;"
                 :: "r"(dst), "l"(src) : "memory");
}
__device__ __forceinline__ void cp_commit() {
    asm volatile("cp.async.commit_group;" ::: "memory");
}
template <int N>
__device__ __forceinline__ void cp_wait() {
    asm volatile("cp.async.wait_group %0;" :: "n"(N) : "memory");
}
__device__ __forceinline__ uint32_t packh(float a, float b) {
    __half2 h = __floats2half2_rn(a, b);
    return *(uint32_t*)&h;
}

// ======================= fp32 -> fp16 splits (fused) ========================
#define NX4 (TS * DIM / 4)
#define NW4 (DIM * DIM / 4)

__global__ __launch_bounds__(256)
void split_all(const float* __restrict__ x,
               const float* __restrict__ qw, const float* __restrict__ kw,
               const float* __restrict__ vw, const float* __restrict__ ow,
               __half* __restrict__ xf,
               __half* __restrict__ wfh, __half* __restrict__ wfl) {
    int i = blockIdx.x * 256 + threadIdx.x;
    int z = blockIdx.y;
    if (z == 0) {
        if (i >= NX4) return;
        float4 v = ((const float4*)x)[i];
        *(uint32_t*)(xf + 4 * (size_t)i)     = packh(v.x, v.y);
        *(uint32_t*)(xf + 4 * (size_t)i + 2) = packh(v.z, v.w);
    } else {
        if (i >= NW4) return;
        const float* in = (z == 1) ? qw : (z == 2) ? kw : (z == 3) ? vw : ow;
        float4 v = ((const float4*)in)[i];
        __half h0 = __float2half_rn(v.x), h1 = __float2half_rn(v.y);
        __half h2 = __float2half_rn(v.z), h3 = __float2half_rn(v.w);
        __half2 H0; H0.x = h0; H0.y = h1;
        __half2 H1; H1.x = h2; H1.y = h3;
        uint32_t l0 = packh(v.x - __half2float(h0), v.y - __half2float(h1));
        uint32_t l1 = packh(v.z - __half2float(h2), v.w - __half2float(h3));
        size_t base = (size_t)(z - 1) * DIM * DIM + 4 * (size_t)i;
        *(uint32_t*)(wfh + base)     = *(uint32_t*)&H0;
        *(uint32_t*)(wfh + base + 2) = *(uint32_t*)&H1;
        *(uint32_t*)(wfl + base)     = l0;
        *(uint32_t*)(wfl + base + 2) = l1;
    }
}

// ======================= mma.sync fp16 2-term GEMM core =====================
// C = A @ (Wh + Wl)^T + bias; A single fp16. 256 threads, 8 warps (2M x 4N),
// 2-stage cp.async ring of {A, Wh, Wl}; 60KB smem -> 2 CTAs/SM.
#define SSTR 40
#define TILE_E (128 * SSTR)
#define TILE_B (TILE_E * 2)
#define GSTAGE_E (3 * TILE_E)
#define GEMM_SMEM_BYTES (2 * GSTAGE_E * 2)   // 61440

struct GemmOut {
    float acc[4][4][4];
};

__device__ __forceinline__ void gemm_core_h(
    const __half* __restrict__ A,
    const __half* __restrict__ Wh, const __half* __restrict__ Wl,
    int m0, int n0, int K, __half* sm, GemmOut& out) {
    const int tid  = threadIdx.x;
    const int warp = tid >> 5, lane = tid & 31;
    const int wm   = warp & 1;
    const int wn   = warp >> 1;
    const uint32_t sbase = s2u(sm);

#pragma unroll
    for (int i = 0; i < 4; i++)
#pragma unroll
        for (int j = 0; j < 4; j++)
#pragma unroll
            for (int k = 0; k < 4; k++) out.acc[i][j][k] = 0.f;

    const __half* srcs[3] = {A, Wh, Wl};

    auto issue_chunk = [&](int c, int s) {
#pragma unroll
        for (int j = 0; j < 6; j++) {
            int i = tid + j * 256;            // 0..1535
            int arr = i >> 9;
            int idx = i & 511;
            int row = idx >> 2, seg = idx & 3;
            const __half* src = srcs[arr] +
                (size_t)((arr == 0 ? m0 : n0) + row) * K + c * 32 + seg * 8;
            uint32_t dst = sbase + (uint32_t)(s * GSTAGE_E + arr * TILE_E + row * SSTR + seg * 8) * 2;
            cp16(dst, src);
        }
        cp_commit();
    };

    const int NC = K / 32;
    issue_chunk(0, 0);

    const uint32_t arow = (uint32_t)(wm * 64 + (lane & 15));
    const uint32_t acol = (uint32_t)((lane >> 4) * 16);
    const uint32_t bro  = (uint32_t)((lane & 7) + 8 * ((lane >> 4) & 1));
    const uint32_t bco  = (uint32_t)(((lane >> 3) & 1) * 16);

    for (int c = 0; c < NC; c++) {
        cp_wait<0>();
        __syncthreads();
        if (c + 1 < NC) issue_chunk(c + 1, (c + 1) & 1);
        const uint32_t bb = sbase + (uint32_t)((c & 1) * GSTAGE_E) * 2;
#pragma unroll
        for (int ks = 0; ks < 2; ks++) {
            uint32_t aF[4][4], bH[8], bL[8];
            const uint32_t aoff = arow * (SSTR * 2) + ks * 32 + acol;
#pragma unroll
            for (int mt = 0; mt < 4; mt++)
                ldsm_x4(aF[mt], bb + 0 * TILE_B + aoff + mt * 16 * (SSTR * 2));
#pragma unroll
            for (int p = 0; p < 2; p++) {
                uint32_t boff = (uint32_t)(wn * 32 + p * 16 + bro) * (SSTR * 2) + ks * 32 + bco;
                ldsm_x4(&bH[4 * p], bb + 1 * TILE_B + boff);
            }
#pragma unroll
            for (int mt = 0; mt < 4; mt++)
#pragma unroll
                for (int nt = 0; nt < 4; nt++)
                    mma16816h(out.acc[mt][nt], aF[mt], &bH[2 * nt]);
#pragma unroll
            for (int p = 0; p < 2; p++) {
                uint32_t boff = (uint32_t)(wn * 32 + p * 16 + bro) * (SSTR * 2) + ks * 32 + bco;
                ldsm_x4(&bL[4 * p], bb + 2 * TILE_B + boff);
            }
#pragma unroll
            for (int mt = 0; mt < 4; mt++)
#pragma unroll
                for (int nt = 0; nt < 4; nt++)
                    mma16816h(out.acc[mt][nt], aF[mt], &bL[2 * nt]);
        }
    }
}

// ---- fused QKV projection: z = 0 (Q, f32) / 1 (K, f32) / 2 (V, fp16) ----
__global__ __launch_bounds__(256, 2)
void gemm_qkv(const __half* __restrict__ xf,
              const __half* __restrict__ wfh, const __half* __restrict__ wfl,
              const float* __restrict__ qb, const float* __restrict__ kb,
              const float* __restrict__ vb,
              float* __restrict__ gq, float* __restrict__ gk,
              __half* __restrict__ vf) {
    extern __shared__ __half smg[];
    const int z  = blockIdx.z;
    const int m0 = blockIdx.y * 128, n0 = blockIdx.x * 128;
    const size_t WSZ = (size_t)DIM * DIM;
    const float* bias = (z == 0) ? qb : (z == 1) ? kb : vb;

    GemmOut out;
    gemm_core_h(xf, wfh + (size_t)z * WSZ, wfl + (size_t)z * WSZ,
                m0, n0, DIM, smg, out);

    const int warp = threadIdx.x >> 5, lane = threadIdx.x & 31;
    const int row_base = m0 + (warp & 1) * 64 + (lane >> 2);
    const int col_base = n0 + (warp >> 1) * 32 + (lane & 3) * 2;
    float* Cf = (z == 0) ? gq : gk;
#pragma unroll
    for (int mt = 0; mt < 4; mt++) {
#pragma unroll
        for (int nt = 0; nt < 4; nt++) {
            int r = row_base + mt * 16;
            int cc = col_base + nt * 8;
            float bx = bias[cc], by = bias[cc + 1];
            float v00 = out.acc[mt][nt][0] + bx, v01 = out.acc[mt][nt][1] + by;
            float v10 = out.acc[mt][nt][2] + bx, v11 = out.acc[mt][nt][3] + by;
            if (z < 2) {
                *(float2*)(Cf + (size_t)r * DIM + cc)       = make_float2(v00, v01);
                *(float2*)(Cf + (size_t)(r + 8) * DIM + cc) = make_float2(v10, v11);
            } else {
                *(uint32_t*)(vf + (size_t)r * DIM + cc)       = packh(v00, v01);
                *(uint32_t*)(vf + (size_t)(r + 8) * DIM + cc) = packh(v10, v11);
            }
        }
    }
}

// ---- O projection (f32 out) ----
__global__ __launch_bounds__(256, 2)
void gemm_o(const __half* __restrict__ A,
            const __half* __restrict__ Wh, const __half* __restrict__ Wl,
            const float* __restrict__ bias, float* __restrict__ Cf) {
    extern __shared__ __half smg[];
    const int m0 = blockIdx.y * 128, n0 = blockIdx.x * 128;
    GemmOut out;
    gemm_core_h(A, Wh, Wl, m0, n0, DIM, smg, out);

    const int warp = threadIdx.x >> 5, lane = threadIdx.x & 31;
    const int row_base = m0 + (warp & 1) * 64 + (lane >> 2);
    const int col_base = n0 + (warp >> 1) * 32 + (lane & 3) * 2;
#pragma unroll
    for (int mt = 0; mt < 4; mt++) {
#pragma unroll
        for (int nt = 0; nt < 4; nt++) {
            int r = row_base + mt * 16;
            int cc = col_base + nt * 8;
            float bx = bias[cc], by = bias[cc + 1];
            *(float2*)(Cf + (size_t)r * DIM + cc) =
                make_float2(out.acc[mt][nt][0] + bx, out.acc[mt][nt][1] + by);
            *(float2*)(Cf + (size_t)(r + 8) * DIM + cc) =
                make_float2(out.acc[mt][nt][2] + bx, out.acc[mt][nt][3] + by);
        }
    }
}

// ======================= RMSNorm + RoPE =======================
// Q -> single fp16 (pre-scaled by SCALE).  K -> fp16 hi/lo.
__global__ __launch_bounds__(256)
void norm_rope_kernel(const float* __restrict__ q, const float* __restrict__ k,
                      const float* __restrict__ freqs,
                      const float* __restrict__ nqw, const float* __restrict__ nkw,
                      __half* __restrict__ QF,
                      __half* __restrict__ KFH, __half* __restrict__ KFL) {
    const int row = blockIdx.x;
    const int isq = (blockIdx.y == 0);
    const float* x = (isq ? q : k) + (size_t)row * DIM;
    const float* w = isq ? nqw : nkw;
    const float sc = isq ? SCALE : 1.f;
    const int tid = threadIdx.x;

    float ss = 0.f;
    for (int i = tid; i < DIM; i += 256) { float v = x[i]; ss += v * v; }
#pragma unroll
    for (int o = 16; o > 0; o >>= 1) ss += __shfl_xor_sync(~0u, ss, o);
    __shared__ float warpsum[8];
    if ((tid & 31) == 0) warpsum[tid >> 5] = ss;
    __syncthreads();
    float tot = 0.f;
#pragma unroll
    for (int i = 0; i < 8; i++) tot += warpsum[i];
    const float rs = rsqrtf(tot / (float)DIM + EPS);

    const int tv = row % VS;
    const int f  = tv / TPF;
    const int r  = tv % TPF;
    const int hh = r / NW;
    const int ww = r % NW;

    for (int p = tid; p < DIM / 2; p += 256) {
        int c = p & 63;
        int idx = (c < 22) ? f : ((c < 43) ? hh : ww);
        float ang = freqs[idx * 64 + c];
        float sn, cs;
        sincosf(ang, &sn, &cs);
        float x0 = x[2 * p]     * rs * w[2 * p];
        float x1 = x[2 * p + 1] * rs * w[2 * p + 1];
        float r0 = (x0 * cs - x1 * sn) * sc;
        float r1 = (x0 * sn + x1 * cs) * sc;
        if (isq) {
            *(uint32_t*)(QF + (size_t)row * DIM + 2 * p) = packh(r0, r1);
        } else {
            uint32_t h = packh(r0, r1);
            __half2 H = *(__half2*)&h;
            uint32_t l = packh(r0 - __half2float(H.x), r1 - __half2float(H.y));
            *(uint32_t*)(KFH + (size_t)row * DIM + 2 * p) = h;
            *(uint32_t*)(KFL + (size_t)row * DIM + 2 * p) = l;
        }
    }
}

// ============== mma.sync flash attention (fp16, key-split) =================
// 64 queries x 1 head per block, 8 warps = 4 row-groups x 2 key-halves.
// QK: S = Q*Kh + Q*Kl (2-term; logits amplify K rounding, so K stays split).
// PV: O += Ph*V (1-term; P<=1 so fp16 rounding of P costs <=2^-11 on O).
#define AQB  64
#define ASTR 136
#define AQR  (AQB * ASTR)
#define ATL  (32 * ASTR)
#define ASTAGE (3 * ATL)
#define ATT_SMEM_BYTES ((AQR + 2 * ASTAGE) * 2)   // 69632

__global__ __launch_bounds__(256, 2)
void attn_mma(const __half* __restrict__ Qf,
              const __half* __restrict__ Kfh, const __half* __restrict__ Kfl,
              const __half* __restrict__ Vf,
              __half* __restrict__ Of) {
    extern __shared__ __half smh[];
    const uint32_t sbase = s2u(smh);
    const int head = blockIdx.y;
    const int q0   = blockIdx.x * AQB;
    const int v    = q0 / VS;
    const int f    = (q0 % VS) / TPF;
    const int col0 = head * HD;
    const int tid  = threadIdx.x;
    const int warp = tid >> 5, lane = tid & 31;
    const int g    = warp >> 1;
    const int h    = warp & 1;

    for (int i = tid; i < AQB * 16; i += 256) {
        int r = i >> 4, seg = i & 15;
        *(uint4*)&smh[r * ASTR + seg * 8] =
            *(const uint4*)&Qf[(size_t)(q0 + r) * DIM + col0 + seg * 8];
    }

    const int baseA = v * VS;
    const int baseB = (1 - v) * VS + f * TPF;
    const int NT = 70;

    const __half* ptrs[3] = {Kfh, Kfl, Vf};

    auto issue_tile = [&](int t, int s) {
        int kb = (t < 56) ? (baseA + t * 32) : (baseB + (t - 56) * 32);
#pragma unroll
        for (int j = 0; j < 6; j++) {
            int i = tid + j * 256;
            int arr = i >> 9;
            int idx = i & 511;
            int r = idx >> 4, seg = idx & 15;
            const __half* src = ptrs[arr] + (size_t)(kb + r) * DIM + col0 + seg * 8;
            uint32_t dst = sbase + (uint32_t)(AQR + s * ASTAGE + arr * ATL + r * ASTR + seg * 8) * 2;
            cp16(dst, src);
        }
        cp_commit();
    };

    issue_tile(0, 0);

    float m[2] = {-1e30f, -1e30f};
    float l[2] = {0.f, 0.f};
    float acc[16][4];
#pragma unroll
    for (int nt = 0; nt < 16; nt++)
#pragma unroll
        for (int j = 0; j < 4; j++) acc[nt][j] = 0.f;

    const uint32_t q_goff = (uint32_t)(g * 16 + (lane & 15)) * (ASTR * 2)
                          + (uint32_t)((lane >> 4) * 16);
    const uint32_t k_bro  = (uint32_t)(h * 16 + (lane & 7) + 8 * ((lane >> 4) & 1));
    const uint32_t k_bco  = (uint32_t)(((lane >> 3) & 1) * 16);
    const uint32_t v_row  = (uint32_t)(h * 16 + (lane & 15));
    const uint32_t v_cofs = (uint32_t)(8 * ((lane >> 4) & 1));

    for (int t = 0; t < NT; t++) {
        cp_wait<0>();
        __syncthreads();
        if (t + 1 < NT) issue_tile(t + 1, (t + 1) & 1);

        const uint32_t st = sbase + (uint32_t)(AQR + (t & 1) * ASTAGE) * 2;
        const uint32_t khb = st, klb = st + ATL * 2, vhb = st + 2 * ATL * 2;

        float Sa[2][4], Sb[2][4];
#pragma unroll
        for (int nt = 0; nt < 2; nt++)
#pragma unroll
            for (int j = 0; j < 4; j++) { Sa[nt][j] = 0.f; Sb[nt][j] = 0.f; }

#pragma unroll
        for (int ks = 0; ks < 8; ks++) {
            uint32_t aQ[4], bKh[4], bKl[4];
            ldsm_x4(aQ, sbase + q_goff + ks * 32);
            uint32_t boff = k_bro * (ASTR * 2) + ks * 32 + k_bco;
            ldsm_x4(bKh, khb + boff);
            ldsm_x4(bKl, klb + boff);
            mma16816h(Sa[0], aQ, &bKh[0]);
            mma16816h(Sa[1], aQ, &bKh[2]);
            mma16816h(Sb[0], aQ, &bKl[0]);
            mma16816h(Sb[1], aQ, &bKl[2]);
        }

        float S[2][4];
#pragma unroll
        for (int nt = 0; nt < 2; nt++)
#pragma unroll
            for (int j = 0; j < 4; j++) S[nt][j] = Sa[nt][j] + Sb[nt][j];

        float mn[2], corr[2];
#pragma unroll
        for (int j = 0; j < 2; j++) {
            float mx = fmaxf(fmaxf(S[0][2 * j], S[0][2 * j + 1]),
                             fmaxf(S[1][2 * j], S[1][2 * j + 1]));
            mx = fmaxf(mx, __shfl_xor_sync(~0u, mx, 1));
            mx = fmaxf(mx, __shfl_xor_sync(~0u, mx, 2));
            mn[j] = fmaxf(m[j], mx);
            corr[j] = __expf(m[j] - mn[j]);
        }
        bool resc = !__all_sync(~0u, (mn[0] == m[0]) && (mn[1] == m[1]));
        m[0] = mn[0]; m[1] = mn[1];

        uint32_t ph[2][2];
#pragma unroll
        for (int j = 0; j < 2; j++) {
            float rs = 0.f;
#pragma unroll
            for (int nt = 0; nt < 2; nt++) {
                float e0 = __expf(S[nt][2 * j]     - mn[j]);
                float e1 = __expf(S[nt][2 * j + 1] - mn[j]);
                S[nt][2 * j] = e0; S[nt][2 * j + 1] = e1;
                rs += e0 + e1;
            }
            rs += __shfl_xor_sync(~0u, rs, 1);
            rs += __shfl_xor_sync(~0u, rs, 2);
            l[j] = l[j] * corr[j] + rs;
        }
        if (resc) {
#pragma unroll
            for (int nt = 0; nt < 16; nt++) {
                acc[nt][0] *= corr[0]; acc[nt][1] *= corr[0];
                acc[nt][2] *= corr[1]; acc[nt][3] *= corr[1];
            }
        }
#pragma unroll
        for (int nt = 0; nt < 2; nt++)
#pragma unroll
            for (int j = 0; j < 2; j++)
                ph[nt][j] = packh(S[nt][2 * j], S[nt][2 * j + 1]);

        // ---- out += Ph * V (single-term PV) ----
        uint32_t aPh[4] = {ph[0][0], ph[0][1], ph[1][0], ph[1][1]};
#pragma unroll
        for (int dp = 0; dp < 8; dp++) {
            uint32_t bV[4];
            uint32_t voff = v_row * (ASTR * 2) + (uint32_t)(dp * 16 + v_cofs) * 2;
            ldsm_x4_t(bV, vhb + voff);
            mma16816h(acc[2 * dp],     aPh, &bV[0]);
            mma16816h(acc[2 * dp + 1], aPh, &bV[2]);
        }
    }

    // ---- merge warp pairs (h=1 publishes, h=0 combines) ----
    __syncthreads();
    float* ex = (float*)smh;
    if (h == 1) {
        float* d = ex + (g * 32 + lane) * 68;
        d[0] = m[0]; d[1] = m[1]; d[2] = l[0]; d[3] = l[1];
#pragma unroll
        for (int nt = 0; nt < 16; nt++) {
            d[4 + 4 * nt + 0] = acc[nt][0];
            d[4 + 4 * nt + 1] = acc[nt][1];
            d[4 + 4 * nt + 2] = acc[nt][2];
            d[4 + 4 * nt + 3] = acc[nt][3];
        }
    }
    __syncthreads();
    if (h == 0) {
        const float* d = ex + (g * 32 + lane) * 68;
        float pm[2] = {d[0], d[1]};
        float pll[2] = {d[2], d[3]};
        float a[2], b[2], inv[2];
#pragma unroll
        for (int j = 0; j < 2; j++) {
            float M = fmaxf(m[j], pm[j]);
            a[j] = __expf(m[j] - M);
            b[j] = __expf(pm[j] - M);
            inv[j] = 1.f / (a[j] * l[j] + b[j] * pll[j]);
        }
#pragma unroll
        for (int j = 0; j < 2; j++) {
            int row = q0 + g * 16 + (lane >> 2) + 8 * j;
#pragma unroll
            for (int nt = 0; nt < 16; nt++) {
                float o0 = (a[j] * acc[nt][2 * j]     + b[j] * d[4 + 4 * nt + 2 * j])     * inv[j];
                float o1 = (a[j] * acc[nt][2 * j + 1] + b[j] * d[4 + 4 * nt + 2 * j + 1]) * inv[j];
                size_t off = (size_t)row * DIM + col0 + nt * 8 + 2 * (lane & 3);
                *(uint32_t*)(Of + off) = packh(o0, o1);
            }
        }
    }
}

// ======================= launch =======================
extern "C" void kernel_launch(void* const* d_in, const int* in_sizes, int n_in,
                              void* d_out, int out_size) {
    const float* x     = (const float*)d_in[0];
    const float* freqs = (const float*)d_in[1];
    const float* q_w   = (const float*)d_in[2];
    const float* q_b   = (const float*)d_in[3];
    const float* k_w   = (const float*)d_in[4];
    const float* k_b   = (const float*)d_in[5];
    const float* v_w   = (const float*)d_in[6];
    const float* v_b   = (const float*)d_in[7];
    const float* o_w   = (const float*)d_in[8];
    const float* o_b   = (const float*)d_in[9];
    const float* nqw   = (const float*)d_in[10];
    const float* nkw   = (const float*)d_in[11];

    float *gq, *gk;
    __half *xf, *qf, *kfh, *kfl, *vf, *of, *wfh, *wfl;
    cudaGetSymbolAddress((void**)&gq, g_q);
    cudaGetSymbolAddress((void**)&gk, g_k);
    cudaGetSymbolAddress((void**)&xf, g_xf);
    cudaGetSymbolAddress((void**)&qf, g_qf);
    cudaGetSymbolAddress((void**)&kfh, g_kfh);
    cudaGetSymbolAddress((void**)&kfl, g_kfl);
    cudaGetSymbolAddress((void**)&vf, g_vf);
    cudaGetSymbolAddress((void**)&of, g_of);
    cudaGetSymbolAddress((void**)&wfh, g_wfh);
    cudaGetSymbolAddress((void**)&wfl, g_wfl);

    const size_t WSZ = (size_t)DIM * DIM;
    __half *owfh = wfh + 3 * WSZ, *owfl = wfl + 3 * WSZ;

    split_all<<<dim3((NX4 + 255) / 256, 5), 256>>>(x, q_w, k_w, v_w, o_w, xf, wfh, wfl);

    cudaFuncSetAttribute(gemm_qkv, cudaFuncAttributeMaxDynamicSharedMemorySize,
                         GEMM_SMEM_BYTES);
    cudaFuncSetAttribute(gemm_o, cudaFuncAttributeMaxDynamicSharedMemorySize,
                         GEMM_SMEM_BYTES);
    gemm_qkv<<<dim3(DIM / 128, TS / 128, 3), 256, GEMM_SMEM_BYTES>>>(
        xf, wfh, wfl, q_b, k_b, v_b, gq, gk, vf);

    norm_rope_kernel<<<dim3(TS, 2), 256>>>(gq, gk, freqs, nqw, nkw, qf, kfh, kfl);

    cudaFuncSetAttribute(attn_mma, cudaFuncAttributeMaxDynamicSharedMemorySize,
                         ATT_SMEM_BYTES);
    attn_mma<<<dim3(TS / AQB, NH), 256, ATT_SMEM_BYTES>>>(qf, kfh, kfl, vf, of);

    gemm_o<<<dim3(DIM / 128, TS / 128), 256, GEMM_SMEM_BYTES>>>(
        of, owfh, owfl, o_b, (float*)d_out);
}

// round 16
// speedup vs baseline: 1.6482x; 1.1202x over previous
#include <cuda_runtime.h>
#include <cuda_bf16.h>
#include <cuda_fp16.h>
#include <cstdint>

#define TS   3584
#define DIM  1536
#define NH   12
#define HD   128
#define VS   1792
#define TPF  448
#define NW   28
#define EPS  1e-6f
#define SCALE 0.08838834764831845f   // 1/sqrt(128)

// -------- scratch (device globals; no allocations allowed) --------
__device__ float g_q[(size_t)TS * DIM];
__device__ float g_k[(size_t)TS * DIM];
__device__ __half g_xf[(size_t)TS * DIM];     // X single fp16
__device__ __half g_qf[(size_t)TS * DIM];     // Q single fp16 (pre-scaled)
__device__ __half g_kf[(size_t)TS * DIM];     // K single fp16
__device__ __half g_vf[(size_t)TS * DIM];     // V single fp16
__device__ __half g_of[(size_t)TS * DIM];     // attention out, single fp16
__device__ __half g_wfh[4][(size_t)DIM * DIM]; // weights fp16 hi
__device__ __half g_wfl[4][(size_t)DIM * DIM]; // weights fp16 lo

// ======================= PTX helpers =======================
__device__ __forceinline__ uint32_t s2u(const void* p) {
    uint32_t a;
    asm("{ .reg .u64 t; cvta.to.shared.u64 t, %1; cvt.u32.u64 %0, t; }"
        : "=r"(a) : "l"(p));
    return a;
}
__device__ __forceinline__ void ldsm_x4(uint32_t* r, uint32_t addr) {
    asm volatile("ldmatrix.sync.aligned.m8n8.x4.shared.b16 {%0,%1,%2,%3}, [%4];"
                 : "=r"(r[0]), "=r"(r[1]), "=r"(r[2]), "=r"(r[3]) : "r"(addr));
}
__device__ __forceinline__ void ldsm_x4_t(uint32_t* r, uint32_t addr) {
    asm volatile("ldmatrix.sync.aligned.m8n8.x4.trans.shared.b16 {%0,%1,%2,%3}, [%4];"
                 : "=r"(r[0]), "=r"(r[1]), "=r"(r[2]), "=r"(r[3]) : "r"(addr));
}
__device__ __forceinline__ void mma16816h(float* c, const uint32_t* a, const uint32_t* b) {
    asm volatile(
        "mma.sync.aligned.m16n8k16.row.col.f32.f16.f16.f32 "
        "{%0,%1,%2,%3}, {%4,%5,%6,%7}, {%8,%9}, {%0,%1,%2,%3};"
        : "+f"(c[0]), "+f"(c[1]), "+f"(c[2]), "+f"(c[3])
        : "r"(a[0]), "r"(a[1]), "r"(a[2]), "r"(a[3]), "r"(b[0]), "r"(b[1]));
}
__device__ __forceinline__ void cp16(uint32_t dst, const void* src) {
    asm volatile("cp.async.ca.shared.global [%0], [%1], 16;"
                 :: "r"(dst), "l"(src) : "memory");
}
__device__ __forceinline__ void cp_commit() {
    asm volatile("cp.async.commit_group;" ::: "memory");
}
template <int N>
__device__ __forceinline__ void cp_wait() {
    asm volatile("cp.async.wait_group %0;" :: "n"(N) : "memory");
}
__device__ __forceinline__ uint32_t packh(float a, float b) {
    __half2 h = __floats2half2_rn(a, b);
    return *(uint32_t*)&h;
}

// ======================= fp32 -> fp16 splits (fused) ========================
#define NX4 (TS * DIM / 4)
#define NW4 (DIM * DIM / 4)

__global__ __launch_bounds__(256)
void split_all(const float* __restrict__ x,
               const float* __restrict__ qw, const float* __restrict__ kw,
               const float* __restrict__ vw, const float* __restrict__ ow,
               __half* __restrict__ xf,
               __half* __restrict__ wfh, __half* __restrict__ wfl) {
    int i = blockIdx.x * 256 + threadIdx.x;
    int z = blockIdx.y;
    if (z == 0) {
        if (i >= NX4) return;
        float4 v = ((const float4*)x)[i];
        *(uint32_t*)(xf + 4 * (size_t)i)     = packh(v.x, v.y);
        *(uint32_t*)(xf + 4 * (size_t)i + 2) = packh(v.z, v.w);
    } else {
        if (i >= NW4) return;
        const float* in = (z == 1) ? qw : (z == 2) ? kw : (z == 3) ? vw : ow;
        float4 v = ((const float4*)in)[i];
        __half h0 = __float2half_rn(v.x), h1 = __float2half_rn(v.y);
        __half h2 = __float2half_rn(v.z), h3 = __float2half_rn(v.w);
        __half2 H0; H0.x = h0; H0.y = h1;
        __half2 H1; H1.x = h2; H1.y = h3;
        uint32_t l0 = packh(v.x - __half2float(h0), v.y - __half2float(h1));
        uint32_t l1 = packh(v.z - __half2float(h2), v.w - __half2float(h3));
        size_t base = (size_t)(z - 1) * DIM * DIM + 4 * (size_t)i;
        *(uint32_t*)(wfh + base)     = *(uint32_t*)&H0;
        *(uint32_t*)(wfh + base + 2) = *(uint32_t*)&H1;
        *(uint32_t*)(wfl + base)     = l0;
        *(uint32_t*)(wfl + base + 2) = l1;
    }
}

// ======================= mma.sync fp16 2-term GEMM core =====================
// C = A @ (Wh + Wl)^T + bias; A single fp16. 256 threads, 8 warps (2M x 4N),
// 2-stage cp.async ring of {A, Wh, Wl}; 60KB smem -> 2 CTAs/SM.
#define SSTR 40
#define TILE_E (128 * SSTR)
#define TILE_B (TILE_E * 2)
#define GSTAGE_E (3 * TILE_E)
#define GEMM_SMEM_BYTES (2 * GSTAGE_E * 2)   // 61440

struct GemmOut {
    float acc[4][4][4];
};

__device__ __forceinline__ void gemm_core_h(
    const __half* __restrict__ A,
    const __half* __restrict__ Wh, const __half* __restrict__ Wl,
    int m0, int n0, int K, __half* sm, GemmOut& out) {
    const int tid  = threadIdx.x;
    const int warp = tid >> 5, lane = tid & 31;
    const int wm   = warp & 1;
    const int wn   = warp >> 1;
    const uint32_t sbase = s2u(sm);

#pragma unroll
    for (int i = 0; i < 4; i++)
#pragma unroll
        for (int j = 0; j < 4; j++)
#pragma unroll
            for (int k = 0; k < 4; k++) out.acc[i][j][k] = 0.f;

    const __half* srcs[3] = {A, Wh, Wl};

    auto issue_chunk = [&](int c, int s) {
#pragma unroll
        for (int j = 0; j < 6; j++) {
            int i = tid + j * 256;            // 0..1535
            int arr = i >> 9;
            int idx = i & 511;
            int row = idx >> 2, seg = idx & 3;
            const __half* src = srcs[arr] +
                (size_t)((arr == 0 ? m0 : n0) + row) * K + c * 32 + seg * 8;
            uint32_t dst = sbase + (uint32_t)(s * GSTAGE_E + arr * TILE_E + row * SSTR + seg * 8) * 2;
            cp16(dst, src);
        }
        cp_commit();
    };

    const int NC = K / 32;
    issue_chunk(0, 0);

    const uint32_t arow = (uint32_t)(wm * 64 + (lane & 15));
    const uint32_t acol = (uint32_t)((lane >> 4) * 16);
    const uint32_t bro  = (uint32_t)((lane & 7) + 8 * ((lane >> 4) & 1));
    const uint32_t bco  = (uint32_t)(((lane >> 3) & 1) * 16);

    for (int c = 0; c < NC; c++) {
        cp_wait<0>();
        __syncthreads();
        if (c + 1 < NC) issue_chunk(c + 1, (c + 1) & 1);
        const uint32_t bb = sbase + (uint32_t)((c & 1) * GSTAGE_E) * 2;
#pragma unroll
        for (int ks = 0; ks < 2; ks++) {
            uint32_t aF[4][4], bH[8], bL[8];
            const uint32_t aoff = arow * (SSTR * 2) + ks * 32 + acol;
#pragma unroll
            for (int mt = 0; mt < 4; mt++)
                ldsm_x4(aF[mt], bb + 0 * TILE_B + aoff + mt * 16 * (SSTR * 2));
#pragma unroll
            for (int p = 0; p < 2; p++) {
                uint32_t boff = (uint32_t)(wn * 32 + p * 16 + bro) * (SSTR * 2) + ks * 32 + bco;
                ldsm_x4(&bH[4 * p], bb + 1 * TILE_B + boff);
            }
#pragma unroll
            for (int mt = 0; mt < 4; mt++)
#pragma unroll
                for (int nt = 0; nt < 4; nt++)
                    mma16816h(out.acc[mt][nt], aF[mt], &bH[2 * nt]);
#pragma unroll
            for (int p = 0; p < 2; p++) {
                uint32_t boff = (uint32_t)(wn * 32 + p * 16 + bro) * (SSTR * 2) + ks * 32 + bco;
                ldsm_x4(&bL[4 * p], bb + 2 * TILE_B + boff);
            }
#pragma unroll
            for (int mt = 0; mt < 4; mt++)
#pragma unroll
                for (int nt = 0; nt < 4; nt++)
                    mma16816h(out.acc[mt][nt], aF[mt], &bL[2 * nt]);
        }
    }
}

// ---- fused QKV projection: z = 0 (Q, f32) / 1 (K, f32) / 2 (V, fp16) ----
__global__ __launch_bounds__(256, 2)
void gemm_qkv(const __half* __restrict__ xf,
              const __half* __restrict__ wfh, const __half* __restrict__ wfl,
              const float* __restrict__ qb, const float* __restrict__ kb,
              const float* __restrict__ vb,
              float* __restrict__ gq, float* __restrict__ gk,
              __half* __restrict__ vf) {
    extern __shared__ __half smg[];
    const int z  = blockIdx.z;
    const int m0 = blockIdx.y * 128, n0 = blockIdx.x * 128;
    const size_t WSZ = (size_t)DIM * DIM;
    const float* bias = (z == 0) ? qb : (z == 1) ? kb : vb;

    GemmOut out;
    gemm_core_h(xf, wfh + (size_t)z * WSZ, wfl + (size_t)z * WSZ,
                m0, n0, DIM, smg, out);

    const int warp = threadIdx.x >> 5, lane = threadIdx.x & 31;
    const int row_base = m0 + (warp & 1) * 64 + (lane >> 2);
    const int col_base = n0 + (warp >> 1) * 32 + (lane & 3) * 2;
    float* Cf = (z == 0) ? gq : gk;
#pragma unroll
    for (int mt = 0; mt < 4; mt++) {
#pragma unroll
        for (int nt = 0; nt < 4; nt++) {
            int r = row_base + mt * 16;
            int cc = col_base + nt * 8;
            float bx = bias[cc], by = bias[cc + 1];
            float v00 = out.acc[mt][nt][0] + bx, v01 = out.acc[mt][nt][1] + by;
            float v10 = out.acc[mt][nt][2] + bx, v11 = out.acc[mt][nt][3] + by;
            if (z < 2) {
                *(float2*)(Cf + (size_t)r * DIM + cc)       = make_float2(v00, v01);
                *(float2*)(Cf + (size_t)(r + 8) * DIM + cc) = make_float2(v10, v11);
            } else {
                *(uint32_t*)(vf + (size_t)r * DIM + cc)       = packh(v00, v01);
                *(uint32_t*)(vf + (size_t)(r + 8) * DIM + cc) = packh(v10, v11);
            }
        }
    }
}

// ---- O projection (f32 out) ----
__global__ __launch_bounds__(256, 2)
void gemm_o(const __half* __restrict__ A,
            const __half* __restrict__ Wh, const __half* __restrict__ Wl,
            const float* __restrict__ bias, float* __restrict__ Cf) {
    extern __shared__ __half smg[];
    const int m0 = blockIdx.y * 128, n0 = blockIdx.x * 128;
    GemmOut out;
    gemm_core_h(A, Wh, Wl, m0, n0, DIM, smg, out);

    const int warp = threadIdx.x >> 5, lane = threadIdx.x & 31;
    const int row_base = m0 + (warp & 1) * 64 + (lane >> 2);
    const int col_base = n0 + (warp >> 1) * 32 + (lane & 3) * 2;
#pragma unroll
    for (int mt = 0; mt < 4; mt++) {
#pragma unroll
        for (int nt = 0; nt < 4; nt++) {
            int r = row_base + mt * 16;
            int cc = col_base + nt * 8;
            float bx = bias[cc], by = bias[cc + 1];
            *(float2*)(Cf + (size_t)r * DIM + cc) =
                make_float2(out.acc[mt][nt][0] + bx, out.acc[mt][nt][1] + by);
            *(float2*)(Cf + (size_t)(r + 8) * DIM + cc) =
                make_float2(out.acc[mt][nt][2] + bx, out.acc[mt][nt][3] + by);
        }
    }
}

// ======================= RMSNorm + RoPE =======================
// Q -> single fp16 (pre-scaled by SCALE).  K -> single fp16.
__global__ __launch_bounds__(256)
void norm_rope_kernel(const float* __restrict__ q, const float* __restrict__ k,
                      const float* __restrict__ freqs,
                      const float* __restrict__ nqw, const float* __restrict__ nkw,
                      __half* __restrict__ QF, __half* __restrict__ KF) {
    const int row = blockIdx.x;
    const int isq = (blockIdx.y == 0);
    const float* x = (isq ? q : k) + (size_t)row * DIM;
    const float* w = isq ? nqw : nkw;
    __half* OF = isq ? QF : KF;
    const float sc = isq ? SCALE : 1.f;
    const int tid = threadIdx.x;

    float ss = 0.f;
    for (int i = tid; i < DIM; i += 256) { float v = x[i]; ss += v * v; }
#pragma unroll
    for (int o = 16; o > 0; o >>= 1) ss += __shfl_xor_sync(~0u, ss, o);
    __shared__ float warpsum[8];
    if ((tid & 31) == 0) warpsum[tid >> 5] = ss;
    __syncthreads();
    float tot = 0.f;
#pragma unroll
    for (int i = 0; i < 8; i++) tot += warpsum[i];
    const float rs = rsqrtf(tot / (float)DIM + EPS);

    const int tv = row % VS;
    const int f  = tv / TPF;
    const int r  = tv % TPF;
    const int hh = r / NW;
    const int ww = r % NW;

    for (int p = tid; p < DIM / 2; p += 256) {
        int c = p & 63;
        int idx = (c < 22) ? f : ((c < 43) ? hh : ww);
        float ang = freqs[idx * 64 + c];
        float sn, cs;
        sincosf(ang, &sn, &cs);
        float x0 = x[2 * p]     * rs * w[2 * p];
        float x1 = x[2 * p + 1] * rs * w[2 * p + 1];
        float r0 = (x0 * cs - x1 * sn) * sc;
        float r1 = (x0 * sn + x1 * cs) * sc;
        *(uint32_t*)(OF + (size_t)row * DIM + 2 * p) = packh(r0, r1);
    }
}

// ============== mma.sync flash attention (fp16 single K/Q/V) ===============
// 64 queries x 1 head per block, 8 warps = 4 row-groups x 2 key-halves.
// QK: S = Q*K (single-term; |S|~O(1) so fp16 K rounding costs ~2e-4 on P).
// PV: O += P*V (single-term).  2-stage ring of {K, V}: 52KB smem.
#define AQB  64
#define ASTR 136
#define AQR  (AQB * ASTR)
#define ATL  (32 * ASTR)
#define ASTAGE (2 * ATL)
#define ATT_SMEM_BYTES ((AQR + 2 * ASTAGE) * 2)   // 52224

__global__ __launch_bounds__(256, 2)
void attn_mma(const __half* __restrict__ Qf, const __half* __restrict__ Kf,
              const __half* __restrict__ Vf,
              __half* __restrict__ Of) {
    extern __shared__ __half smh[];
    const uint32_t sbase = s2u(smh);
    const int head = blockIdx.y;
    const int q0   = blockIdx.x * AQB;
    const int v    = q0 / VS;
    const int f    = (q0 % VS) / TPF;
    const int col0 = head * HD;
    const int tid  = threadIdx.x;
    const int warp = tid >> 5, lane = tid & 31;
    const int g    = warp >> 1;
    const int h    = warp & 1;

    for (int i = tid; i < AQB * 16; i += 256) {
        int r = i >> 4, seg = i & 15;
        *(uint4*)&smh[r * ASTR + seg * 8] =
            *(const uint4*)&Qf[(size_t)(q0 + r) * DIM + col0 + seg * 8];
    }

    const int baseA = v * VS;
    const int baseB = (1 - v) * VS + f * TPF;
    const int NT = 70;

    const __half* ptrs[2] = {Kf, Vf};

    auto issue_tile = [&](int t, int s) {
        int kb = (t < 56) ? (baseA + t * 32) : (baseB + (t - 56) * 32);
#pragma unroll
        for (int j = 0; j < 4; j++) {
            int i = tid + j * 256;        // 0..1023
            int arr = i >> 9;
            int idx = i & 511;
            int r = idx >> 4, seg = idx & 15;
            const __half* src = ptrs[arr] + (size_t)(kb + r) * DIM + col0 + seg * 8;
            uint32_t dst = sbase + (uint32_t)(AQR + s * ASTAGE + arr * ATL + r * ASTR + seg * 8) * 2;
            cp16(dst, src);
        }
        cp_commit();
    };

    issue_tile(0, 0);

    float m[2] = {-1e30f, -1e30f};
    float l[2] = {0.f, 0.f};
    float acc[16][4];
#pragma unroll
    for (int nt = 0; nt < 16; nt++)
#pragma unroll
        for (int j = 0; j < 4; j++) acc[nt][j] = 0.f;

    const uint32_t q_goff = (uint32_t)(g * 16 + (lane & 15)) * (ASTR * 2)
                          + (uint32_t)((lane >> 4) * 16);
    const uint32_t k_bro  = (uint32_t)(h * 16 + (lane & 7) + 8 * ((lane >> 4) & 1));
    const uint32_t k_bco  = (uint32_t)(((lane >> 3) & 1) * 16);
    const uint32_t v_row  = (uint32_t)(h * 16 + (lane & 15));
    const uint32_t v_cofs = (uint32_t)(8 * ((lane >> 4) & 1));

    for (int t = 0; t < NT; t++) {
        cp_wait<0>();
        __syncthreads();
        if (t + 1 < NT) issue_tile(t + 1, (t + 1) & 1);

        const uint32_t st = sbase + (uint32_t)(AQR + (t & 1) * ASTAGE) * 2;
        const uint32_t khb = st, vhb = st + ATL * 2;

        // ---- S = Q * K (single term) ----
        float S[2][4];
#pragma unroll
        for (int nt = 0; nt < 2; nt++)
#pragma unroll
            for (int j = 0; j < 4; j++) S[nt][j] = 0.f;

#pragma unroll
        for (int ks = 0; ks < 8; ks++) {
            uint32_t aQ[4], bK[4];
            ldsm_x4(aQ, sbase + q_goff + ks * 32);
            ldsm_x4(bK, khb + k_bro * (ASTR * 2) + ks * 32 + k_bco);
            mma16816h(S[0], aQ, &bK[0]);
            mma16816h(S[1], aQ, &bK[2]);
        }

        float mn[2], corr[2];
#pragma unroll
        for (int j = 0; j < 2; j++) {
            float mx = fmaxf(fmaxf(S[0][2 * j], S[0][2 * j + 1]),
                             fmaxf(S[1][2 * j], S[1][2 * j + 1]));
            mx = fmaxf(mx, __shfl_xor_sync(~0u, mx, 1));
            mx = fmaxf(mx, __shfl_xor_sync(~0u, mx, 2));
            mn[j] = fmaxf(m[j], mx);
            corr[j] = __expf(m[j] - mn[j]);
        }
        bool resc = !__all_sync(~0u, (mn[0] == m[0]) && (mn[1] == m[1]));
        m[0] = mn[0]; m[1] = mn[1];

        uint32_t ph[2][2];
#pragma unroll
        for (int j = 0; j < 2; j++) {
            float rs = 0.f;
#pragma unroll
            for (int nt = 0; nt < 2; nt++) {
                float e0 = __expf(S[nt][2 * j]     - mn[j]);
                float e1 = __expf(S[nt][2 * j + 1] - mn[j]);
                S[nt][2 * j] = e0; S[nt][2 * j + 1] = e1;
                rs += e0 + e1;
            }
            rs += __shfl_xor_sync(~0u, rs, 1);
            rs += __shfl_xor_sync(~0u, rs, 2);
            l[j] = l[j] * corr[j] + rs;
        }
        if (resc) {
#pragma unroll
            for (int nt = 0; nt < 16; nt++) {
                acc[nt][0] *= corr[0]; acc[nt][1] *= corr[0];
                acc[nt][2] *= corr[1]; acc[nt][3] *= corr[1];
            }
        }
#pragma unroll
        for (int nt = 0; nt < 2; nt++)
#pragma unroll
            for (int j = 0; j < 2; j++)
                ph[nt][j] = packh(S[nt][2 * j], S[nt][2 * j + 1]);

        // ---- out += P * V (single term) ----
        uint32_t aPh[4] = {ph[0][0], ph[0][1], ph[1][0], ph[1][1]};
#pragma unroll
        for (int dp = 0; dp < 8; dp++) {
            uint32_t bV[4];
            uint32_t voff = v_row * (ASTR * 2) + (uint32_t)(dp * 16 + v_cofs) * 2;
            ldsm_x4_t(bV, vhb + voff);
            mma16816h(acc[2 * dp],     aPh, &bV[0]);
            mma16816h(acc[2 * dp + 1], aPh, &bV[2]);
        }
    }

    // ---- merge warp pairs (h=1 publishes, h=0 combines) ----
    __syncthreads();
    float* ex = (float*)smh;
    if (h == 1) {
        float* d = ex + (g * 32 + lane) * 68;
        d[0] = m[0]; d[1] = m[1]; d[2] = l[0]; d[3] = l[1];
#pragma unroll
        for (int nt = 0; nt < 16; nt++) {
            d[4 + 4 * nt + 0] = acc[nt][0];
            d[4 + 4 * nt + 1] = acc[nt][1];
            d[4 + 4 * nt + 2] = acc[nt][2];
            d[4 + 4 * nt + 3] = acc[nt][3];
        }
    }
    __syncthreads();
    if (h == 0) {
        const float* d = ex + (g * 32 + lane) * 68;
        float pm[2] = {d[0], d[1]};
        float pll[2] = {d[2], d[3]};
        float a[2], b[2], inv[2];
#pragma unroll
        for (int j = 0; j < 2; j++) {
            float M = fmaxf(m[j], pm[j]);
            a[j] = __expf(m[j] - M);
            b[j] = __expf(pm[j] - M);
            inv[j] = 1.f / (a[j] * l[j] + b[j] * pll[j]);
        }
#pragma unroll
        for (int j = 0; j < 2; j++) {
            int row = q0 + g * 16 + (lane >> 2) + 8 * j;
#pragma unroll
            for (int nt = 0; nt < 16; nt++) {
                float o0 = (a[j] * acc[nt][2 * j]     + b[j] * d[4 + 4 * nt + 2 * j])     * inv[j];
                float o1 = (a[j] * acc[nt][2 * j + 1] + b[j] * d[4 + 4 * nt + 2 * j + 1]) * inv[j];
                size_t off = (size_t)row * DIM + col0 + nt * 8 + 2 * (lane & 3);
                *(uint32_t*)(Of + off) = packh(o0, o1);
            }
        }
    }
}

// ======================= launch =======================
extern "C" void kernel_launch(void* const* d_in, const int* in_sizes, int n_in,
                              void* d_out, int out_size) {
    const float* x     = (const float*)d_in[0];
    const float* freqs = (const float*)d_in[1];
    const float* q_w   = (const float*)d_in[2];
    const float* q_b   = (const float*)d_in[3];
    const float* k_w   = (const float*)d_in[4];
    const float* k_b   = (const float*)d_in[5];
    const float* v_w   = (const float*)d_in[6];
    const float* v_b   = (const float*)d_in[7];
    const float* o_w   = (const float*)d_in[8];
    const float* o_b   = (const float*)d_in[9];
    const float* nqw   = (const float*)d_in[10];
    const float* nkw   = (const float*)d_in[11];

    float *gq, *gk;
    __half *xf, *qf, *kf, *vf, *of, *wfh, *wfl;
    cudaGetSymbolAddress((void**)&gq, g_q);
    cudaGetSymbolAddress((void**)&gk, g_k);
    cudaGetSymbolAddress((void**)&xf, g_xf);
    cudaGetSymbolAddress((void**)&qf, g_qf);
    cudaGetSymbolAddress((void**)&kf, g_kf);
    cudaGetSymbolAddress((void**)&vf, g_vf);
    cudaGetSymbolAddress((void**)&of, g_of);
    cudaGetSymbolAddress((void**)&wfh, g_wfh);
    cudaGetSymbolAddress((void**)&wfl, g_wfl);

    const size_t WSZ = (size_t)DIM * DIM;
    __half *owfh = wfh + 3 * WSZ, *owfl = wfl + 3 * WSZ;

    split_all<<<dim3((NX4 + 255) / 256, 5), 256>>>(x, q_w, k_w, v_w, o_w, xf, wfh, wfl);

    cudaFuncSetAttribute(gemm_qkv, cudaFuncAttributeMaxDynamicSharedMemorySize,
                         GEMM_SMEM_BYTES);
    cudaFuncSetAttribute(gemm_o, cudaFuncAttributeMaxDynamicSharedMemorySize,
                         GEMM_SMEM_BYTES);
    gemm_qkv<<<dim3(DIM / 128, TS / 128, 3), 256, GEMM_SMEM_BYTES>>>(
        xf, wfh, wfl, q_b, k_b, v_b, gq, gk, vf);

    norm_rope_kernel<<<dim3(TS, 2), 256>>>(gq, gk, freqs, nqw, nkw, qf, kf);

    cudaFuncSetAttribute(attn_mma, cudaFuncAttributeMaxDynamicSharedMemorySize,
                         ATT_SMEM_BYTES);
    attn_mma<<<dim3(TS / AQB, NH), 256, ATT_SMEM_BYTES>>>(qf, kf, vf, of);

    gemm_o<<<dim3(DIM / 128, TS / 128), 256, GEMM_SMEM_BYTES>>>(
        of, owfh, owfl, o_b, (float*)d_out);
}

// round 17
// speedup vs baseline: 2.1618x; 1.3116x over previous
#include <cuda_runtime.h>
#include <cuda_bf16.h>
#include <cuda_fp16.h>
#include <cstdint>

#define TS   3584
#define DIM  1536
#define NH   12
#define HD   128
#define VS   1792
#define TPF  448
#define NW   28
#define EPS  1e-6f
#define SCALE 0.08838834764831845f   // 1/sqrt(128)

// -------- scratch (device globals; no allocations allowed) --------
__device__ float g_q[(size_t)TS * DIM];
__device__ float g_k[(size_t)TS * DIM];
__device__ __half g_xf[(size_t)TS * DIM];     // X single fp16
__device__ __half g_qf[(size_t)TS * DIM];     // Q single fp16 (pre-scaled)
__device__ __half g_kf[(size_t)TS * DIM];     // K single fp16
__device__ __half g_vf[(size_t)TS * DIM];     // V single fp16
__device__ __half g_of[(size_t)TS * DIM];     // attention out, single fp16
__device__ __half g_wf[4][(size_t)DIM * DIM]; // weights single fp16

// ======================= PTX helpers =======================
__device__ __forceinline__ uint32_t s2u(const void* p) {
    uint32_t a;
    asm("{ .reg .u64 t; cvta.to.shared.u64 t, %1; cvt.u32.u64 %0, t; }"
        : "=r"(a) : "l"(p));
    return a;
}
__device__ __forceinline__ void ldsm_x4(uint32_t* r, uint32_t addr) {
    asm volatile("ldmatrix.sync.aligned.m8n8.x4.shared.b16 {%0,%1,%2,%3}, [%4];"
                 : "=r"(r[0]), "=r"(r[1]), "=r"(r[2]), "=r"(r[3]) : "r"(addr));
}
__device__ __forceinline__ void ldsm_x4_t(uint32_t* r, uint32_t addr) {
    asm volatile("ldmatrix.sync.aligned.m8n8.x4.trans.shared.b16 {%0,%1,%2,%3}, [%4];"
                 : "=r"(r[0]), "=r"(r[1]), "=r"(r[2]), "=r"(r[3]) : "r"(addr));
}
__device__ __forceinline__ void mma16816h(float* c, const uint32_t* a, const uint32_t* b) {
    asm volatile(
        "mma.sync.aligned.m16n8k16.row.col.f32.f16.f16.f32 "
        "{%0,%1,%2,%3}, {%4,%5,%6,%7}, {%8,%9}, {%0,%1,%2,%3};"
        : "+f"(c[0]), "+f"(c[1]), "+f"(c[2]), "+f"(c[3])
        : "r"(a[0]), "r"(a[1]), "r"(a[2]), "r"(a[3]), "r"(b[0]), "r"(b[1]));
}
__device__ __forceinline__ void cp16(uint32_t dst, const void* src) {
    asm volatile("cp.async.ca.shared.global [%0], [%1], 16;"
                 :: "r"(dst), "l"(src) : "memory");
}
__device__ __forceinline__ void cp_commit() {
    asm volatile("cp.async.commit_group;" ::: "memory");
}
template <int N>
__device__ __forceinline__ void cp_wait() {
    asm volatile("cp.async.wait_group %0;" :: "n"(N) : "memory");
}
__device__ __forceinline__ uint32_t packh(float a, float b) {
    __half2 h = __floats2half2_rn(a, b);
    return *(uint32_t*)&h;
}

// ======================= fp32 -> fp16 convert (fused) =======================
#define NX4 (TS * DIM / 4)
#define NW4 (DIM * DIM / 4)

__global__ __launch_bounds__(256)
void split_all(const float* __restrict__ x,
               const float* __restrict__ qw, const float* __restrict__ kw,
               const float* __restrict__ vw, const float* __restrict__ ow,
               __half* __restrict__ xf, __half* __restrict__ wf) {
    int i = blockIdx.x * 256 + threadIdx.x;
    int z = blockIdx.y;
    if (z == 0) {
        if (i >= NX4) return;
        float4 v = ((const float4*)x)[i];
        *(uint32_t*)(xf + 4 * (size_t)i)     = packh(v.x, v.y);
        *(uint32_t*)(xf + 4 * (size_t)i + 2) = packh(v.z, v.w);
    } else {
        if (i >= NW4) return;
        const float* in = (z == 1) ? qw : (z == 2) ? kw : (z == 3) ? vw : ow;
        float4 v = ((const float4*)in)[i];
        size_t base = (size_t)(z - 1) * DIM * DIM + 4 * (size_t)i;
        *(uint32_t*)(wf + base)     = packh(v.x, v.y);
        *(uint32_t*)(wf + base + 2) = packh(v.z, v.w);
    }
}

// ======================= mma.sync fp16 GEMM core ============================
// C = A @ W^T + bias, both single fp16. 256 threads, 8 warps (2M x 4N),
// 2-stage cp.async ring of {A, W}; 40KB smem -> 2 CTAs/SM.
#define SSTR 40
#define TILE_E (128 * SSTR)
#define TILE_B (TILE_E * 2)
#define GSTAGE_E (2 * TILE_E)
#define GEMM_SMEM_BYTES (2 * GSTAGE_E * 2)   // 40960

struct GemmOut {
    float acc[4][4][4];
};

__device__ __forceinline__ void gemm_core_h(
    const __half* __restrict__ A, const __half* __restrict__ W,
    int m0, int n0, int K, __half* sm, GemmOut& out) {
    const int tid  = threadIdx.x;
    const int warp = tid >> 5, lane = tid & 31;
    const int wm   = warp & 1;
    const int wn   = warp >> 1;
    const uint32_t sbase = s2u(sm);

#pragma unroll
    for (int i = 0; i < 4; i++)
#pragma unroll
        for (int j = 0; j < 4; j++)
#pragma unroll
            for (int k = 0; k < 4; k++) out.acc[i][j][k] = 0.f;

    const __half* srcs[2] = {A, W};

    auto issue_chunk = [&](int c, int s) {
#pragma unroll
        for (int j = 0; j < 4; j++) {
            int i = tid + j * 256;            // 0..1023
            int arr = i >> 9;
            int idx = i & 511;
            int row = idx >> 2, seg = idx & 3;
            const __half* src = srcs[arr] +
                (size_t)((arr == 0 ? m0 : n0) + row) * K + c * 32 + seg * 8;
            uint32_t dst = sbase + (uint32_t)(s * GSTAGE_E + arr * TILE_E + row * SSTR + seg * 8) * 2;
            cp16(dst, src);
        }
        cp_commit();
    };

    const int NC = K / 32;
    issue_chunk(0, 0);

    const uint32_t arow = (uint32_t)(wm * 64 + (lane & 15));
    const uint32_t acol = (uint32_t)((lane >> 4) * 16);
    const uint32_t bro  = (uint32_t)((lane & 7) + 8 * ((lane >> 4) & 1));
    const uint32_t bco  = (uint32_t)(((lane >> 3) & 1) * 16);

    for (int c = 0; c < NC; c++) {
        cp_wait<0>();
        __syncthreads();
        if (c + 1 < NC) issue_chunk(c + 1, (c + 1) & 1);
        const uint32_t bb = sbase + (uint32_t)((c & 1) * GSTAGE_E) * 2;
#pragma unroll
        for (int ks = 0; ks < 2; ks++) {
            uint32_t aF[4][4], bW[8];
            const uint32_t aoff = arow * (SSTR * 2) + ks * 32 + acol;
#pragma unroll
            for (int mt = 0; mt < 4; mt++)
                ldsm_x4(aF[mt], bb + 0 * TILE_B + aoff + mt * 16 * (SSTR * 2));
#pragma unroll
            for (int p = 0; p < 2; p++) {
                uint32_t boff = (uint32_t)(wn * 32 + p * 16 + bro) * (SSTR * 2) + ks * 32 + bco;
                ldsm_x4(&bW[4 * p], bb + 1 * TILE_B + boff);
            }
#pragma unroll
            for (int mt = 0; mt < 4; mt++)
#pragma unroll
                for (int nt = 0; nt < 4; nt++)
                    mma16816h(out.acc[mt][nt], aF[mt], &bW[2 * nt]);
        }
    }
}

// ---- fused QKV projection: z = 0 (Q, f32) / 1 (K, f32) / 2 (V, fp16) ----
__global__ __launch_bounds__(256, 2)
void gemm_qkv(const __half* __restrict__ xf, const __half* __restrict__ wf,
              const float* __restrict__ qb, const float* __restrict__ kb,
              const float* __restrict__ vb,
              float* __restrict__ gq, float* __restrict__ gk,
              __half* __restrict__ vf) {
    extern __shared__ __half smg[];
    const int z  = blockIdx.z;
    const int m0 = blockIdx.y * 128, n0 = blockIdx.x * 128;
    const size_t WSZ = (size_t)DIM * DIM;
    const float* bias = (z == 0) ? qb : (z == 1) ? kb : vb;

    GemmOut out;
    gemm_core_h(xf, wf + (size_t)z * WSZ, m0, n0, DIM, smg, out);

    const int warp = threadIdx.x >> 5, lane = threadIdx.x & 31;
    const int row_base = m0 + (warp & 1) * 64 + (lane >> 2);
    const int col_base = n0 + (warp >> 1) * 32 + (lane & 3) * 2;
    float* Cf = (z == 0) ? gq : gk;
#pragma unroll
    for (int mt = 0; mt < 4; mt++) {
#pragma unroll
        for (int nt = 0; nt < 4; nt++) {
            int r = row_base + mt * 16;
            int cc = col_base + nt * 8;
            float bx = bias[cc], by = bias[cc + 1];
            float v00 = out.acc[mt][nt][0] + bx, v01 = out.acc[mt][nt][1] + by;
            float v10 = out.acc[mt][nt][2] + bx, v11 = out.acc[mt][nt][3] + by;
            if (z < 2) {
                *(float2*)(Cf + (size_t)r * DIM + cc)       = make_float2(v00, v01);
                *(float2*)(Cf + (size_t)(r + 8) * DIM + cc) = make_float2(v10, v11);
            } else {
                *(uint32_t*)(vf + (size_t)r * DIM + cc)       = packh(v00, v01);
                *(uint32_t*)(vf + (size_t)(r + 8) * DIM + cc) = packh(v10, v11);
            }
        }
    }
}

// ---- O projection (f32 out) ----
__global__ __launch_bounds__(256, 2)
void gemm_o(const __half* __restrict__ A, const __half* __restrict__ W,
            const float* __restrict__ bias, float* __restrict__ Cf) {
    extern __shared__ __half smg[];
    const int m0 = blockIdx.y * 128, n0 = blockIdx.x * 128;
    GemmOut out;
    gemm_core_h(A, W, m0, n0, DIM, smg, out);

    const int warp = threadIdx.x >> 5, lane = threadIdx.x & 31;
    const int row_base = m0 + (warp & 1) * 64 + (lane >> 2);
    const int col_base = n0 + (warp >> 1) * 32 + (lane & 3) * 2;
#pragma unroll
    for (int mt = 0; mt < 4; mt++) {
#pragma unroll
        for (int nt = 0; nt < 4; nt++) {
            int r = row_base + mt * 16;
            int cc = col_base + nt * 8;
            float bx = bias[cc], by = bias[cc + 1];
            *(float2*)(Cf + (size_t)r * DIM + cc) =
                make_float2(out.acc[mt][nt][0] + bx, out.acc[mt][nt][1] + by);
            *(float2*)(Cf + (size_t)(r + 8) * DIM + cc) =
                make_float2(out.acc[mt][nt][2] + bx, out.acc[mt][nt][3] + by);
        }
    }
}

// ======================= RMSNorm + RoPE =======================
// Q -> single fp16 (pre-scaled by SCALE).  K -> single fp16.
__global__ __launch_bounds__(256)
void norm_rope_kernel(const float* __restrict__ q, const float* __restrict__ k,
                      const float* __restrict__ freqs,
                      const float* __restrict__ nqw, const float* __restrict__ nkw,
                      __half* __restrict__ QF, __half* __restrict__ KF) {
    const int row = blockIdx.x;
    const int isq = (blockIdx.y == 0);
    const float* x = (isq ? q : k) + (size_t)row * DIM;
    const float* w = isq ? nqw : nkw;
    __half* OF = isq ? QF : KF;
    const float sc = isq ? SCALE : 1.f;
    const int tid = threadIdx.x;

    float ss = 0.f;
    for (int i = tid; i < DIM; i += 256) { float v = x[i]; ss += v * v; }
#pragma unroll
    for (int o = 16; o > 0; o >>= 1) ss += __shfl_xor_sync(~0u, ss, o);
    __shared__ float warpsum[8];
    if ((tid & 31) == 0) warpsum[tid >> 5] = ss;
    __syncthreads();
    float tot = 0.f;
#pragma unroll
    for (int i = 0; i < 8; i++) tot += warpsum[i];
    const float rs = rsqrtf(tot / (float)DIM + EPS);

    const int tv = row % VS;
    const int f  = tv / TPF;
    const int r  = tv % TPF;
    const int hh = r / NW;
    const int ww = r % NW;

    for (int p = tid; p < DIM / 2; p += 256) {
        int c = p & 63;
        int idx = (c < 22) ? f : ((c < 43) ? hh : ww);
        float ang = freqs[idx * 64 + c];
        float sn, cs;
        sincosf(ang, &sn, &cs);
        float x0 = x[2 * p]     * rs * w[2 * p];
        float x1 = x[2 * p + 1] * rs * w[2 * p + 1];
        float r0 = (x0 * cs - x1 * sn) * sc;
        float r1 = (x0 * sn + x1 * cs) * sc;
        *(uint32_t*)(OF + (size_t)row * DIM + 2 * p) = packh(r0, r1);
    }
}

// ============== mma.sync flash attention (fp16, 64-key tiles) ==============
// 64 queries x 1 head per block, 8 warps = 4 row-groups x 2 key-halves
// (each warp owns 32 keys of a 64-key tile). Q ldsm amortized 2x; softmax
// and barriers run per 64 keys. 2-stage ring of {K, V}: 87KB -> 2 CTAs/SM.
#define AQB  64
#define AKB  64
#define ASTR 136
#define AQR  (AQB * ASTR)
#define ATL  (AKB * ASTR)
#define ASTAGE (2 * ATL)
#define ATT_SMEM_BYTES ((AQR + 2 * ASTAGE) * 2)   // 87040

__global__ __launch_bounds__(256, 2)
void attn_mma(const __half* __restrict__ Qf, const __half* __restrict__ Kf,
              const __half* __restrict__ Vf,
              __half* __restrict__ Of) {
    extern __shared__ __half smh[];
    const uint32_t sbase = s2u(smh);
    const int head = blockIdx.y;
    const int q0   = blockIdx.x * AQB;
    const int v    = q0 / VS;
    const int f    = (q0 % VS) / TPF;
    const int col0 = head * HD;
    const int tid  = threadIdx.x;
    const int warp = tid >> 5, lane = tid & 31;
    const int g    = warp >> 1;           // row group (16 rows)
    const int h    = warp & 1;            // key half (32 keys)

    for (int i = tid; i < AQB * 16; i += 256) {
        int r = i >> 4, seg = i & 15;
        *(uint4*)&smh[r * ASTR + seg * 8] =
            *(const uint4*)&Qf[(size_t)(q0 + r) * DIM + col0 + seg * 8];
    }

    const int baseA = v * VS;
    const int baseB = (1 - v) * VS + f * TPF;
    const int NT = (VS + TPF) / AKB;      // 35

    const __half* ptrs[2] = {Kf, Vf};

    auto issue_tile = [&](int t, int s) {
        int kb = (t < 28) ? (baseA + t * AKB) : (baseB + (t - 28) * AKB);
#pragma unroll
        for (int j = 0; j < 8; j++) {
            int i = tid + j * 256;        // 0..2047
            int arr = i >> 10;
            int idx = i & 1023;
            int r = idx >> 4, seg = idx & 15;
            const __half* src = ptrs[arr] + (size_t)(kb + r) * DIM + col0 + seg * 8;
            uint32_t dst = sbase + (uint32_t)(AQR + s * ASTAGE + arr * ATL + r * ASTR + seg * 8) * 2;
            cp16(dst, src);
        }
        cp_commit();
    };

    issue_tile(0, 0);

    float m[2] = {-1e30f, -1e30f};
    float l[2] = {0.f, 0.f};
    float acc[16][4];
#pragma unroll
    for (int nt = 0; nt < 16; nt++)
#pragma unroll
        for (int j = 0; j < 4; j++) acc[nt][j] = 0.f;

    const uint32_t q_goff = (uint32_t)(g * 16 + (lane & 15)) * (ASTR * 2)
                          + (uint32_t)((lane >> 4) * 16);
    const uint32_t k_bro  = (uint32_t)((lane & 7) + 8 * ((lane >> 4) & 1));
    const uint32_t k_bco  = (uint32_t)(((lane >> 3) & 1) * 16);
    const uint32_t v_row  = (uint32_t)(lane & 15);
    const uint32_t v_cofs = (uint32_t)(8 * ((lane >> 4) & 1));

    for (int t = 0; t < NT; t++) {
        cp_wait<0>();
        __syncthreads();
        if (t + 1 < NT) issue_tile(t + 1, (t + 1) & 1);

        const uint32_t st = sbase + (uint32_t)(AQR + (t & 1) * ASTAGE) * 2;
        const uint32_t khb = st, vhb = st + ATL * 2;

        // ---- S = Q * K over this warp's 32 keys ----
        float S[4][4];
#pragma unroll
        for (int nt = 0; nt < 4; nt++)
#pragma unroll
            for (int j = 0; j < 4; j++) S[nt][j] = 0.f;

#pragma unroll
        for (int ks = 0; ks < 8; ks++) {
            uint32_t aQ[4];
            ldsm_x4(aQ, sbase + q_goff + ks * 32);
#pragma unroll
            for (int p = 0; p < 2; p++) {
                uint32_t bK[4];
                uint32_t boff = (uint32_t)(h * 32 + p * 16 + k_bro) * (ASTR * 2)
                              + ks * 32 + k_bco;
                ldsm_x4(bK, khb + boff);
                mma16816h(S[2 * p],     aQ, &bK[0]);
                mma16816h(S[2 * p + 1], aQ, &bK[2]);
            }
        }

        // ---- online softmax over this warp's 32 keys ----
        float mn[2], corr[2];
#pragma unroll
        for (int j = 0; j < 2; j++) {
            float mx = -1e30f;
#pragma unroll
            for (int nt = 0; nt < 4; nt++)
                mx = fmaxf(mx, fmaxf(S[nt][2 * j], S[nt][2 * j + 1]));
            mx = fmaxf(mx, __shfl_xor_sync(~0u, mx, 1));
            mx = fmaxf(mx, __shfl_xor_sync(~0u, mx, 2));
            mn[j] = fmaxf(m[j], mx);
            corr[j] = __expf(m[j] - mn[j]);
        }
        bool resc = !__all_sync(~0u, (mn[0] == m[0]) && (mn[1] == m[1]));
        m[0] = mn[0]; m[1] = mn[1];

        uint32_t ph[4][2];
#pragma unroll
        for (int j = 0; j < 2; j++) {
            float rs = 0.f;
#pragma unroll
            for (int nt = 0; nt < 4; nt++) {
                float e0 = __expf(S[nt][2 * j]     - mn[j]);
                float e1 = __expf(S[nt][2 * j + 1] - mn[j]);
                S[nt][2 * j] = e0; S[nt][2 * j + 1] = e1;
                rs += e0 + e1;
            }
            rs += __shfl_xor_sync(~0u, rs, 1);
            rs += __shfl_xor_sync(~0u, rs, 2);
            l[j] = l[j] * corr[j] + rs;
        }
        if (resc) {
#pragma unroll
            for (int nt = 0; nt < 16; nt++) {
                acc[nt][0] *= corr[0]; acc[nt][1] *= corr[0];
                acc[nt][2] *= corr[1]; acc[nt][3] *= corr[1];
            }
        }
#pragma unroll
        for (int nt = 0; nt < 4; nt++)
#pragma unroll
            for (int j = 0; j < 2; j++)
                ph[nt][j] = packh(S[nt][2 * j], S[nt][2 * j + 1]);

        // ---- out += P * V over this warp's 32 keys (2 k-chunks of 16) ----
#pragma unroll
        for (int c = 0; c < 2; c++) {
            uint32_t aP[4] = {ph[2 * c][0], ph[2 * c][1], ph[2 * c + 1][0], ph[2 * c + 1][1]};
#pragma unroll
            for (int dp = 0; dp < 8; dp++) {
                uint32_t bV[4];
                uint32_t voff = (uint32_t)(h * 32 + c * 16 + v_row) * (ASTR * 2)
                              + (uint32_t)(dp * 16 + v_cofs) * 2;
                ldsm_x4_t(bV, vhb + voff);
                mma16816h(acc[2 * dp],     aP, &bV[0]);
                mma16816h(acc[2 * dp + 1], aP, &bV[2]);
            }
        }
    }

    // ---- merge warp pairs (h=1 publishes, h=0 combines) ----
    __syncthreads();
    float* ex = (float*)smh;
    if (h == 1) {
        float* d = ex + (g * 32 + lane) * 68;
        d[0] = m[0]; d[1] = m[1]; d[2] = l[0]; d[3] = l[1];
#pragma unroll
        for (int nt = 0; nt < 16; nt++) {
            d[4 + 4 * nt + 0] = acc[nt][0];
            d[4 + 4 * nt + 1] = acc[nt][1];
            d[4 + 4 * nt + 2] = acc[nt][2];
            d[4 + 4 * nt + 3] = acc[nt][3];
        }
    }
    __syncthreads();
    if (h == 0) {
        const float* d = ex + (g * 32 + lane) * 68;
        float pm[2] = {d[0], d[1]};
        float pll[2] = {d[2], d[3]};
        float a[2], b[2], inv[2];
#pragma unroll
        for (int j = 0; j < 2; j++) {
            float M = fmaxf(m[j], pm[j]);
            a[j] = __expf(m[j] - M);
            b[j] = __expf(pm[j] - M);
            inv[j] = 1.f / (a[j] * l[j] + b[j] * pll[j]);
        }
#pragma unroll
        for (int j = 0; j < 2; j++) {
            int row = q0 + g * 16 + (lane >> 2) + 8 * j;
#pragma unroll
            for (int nt = 0; nt < 16; nt++) {
                float o0 = (a[j] * acc[nt][2 * j]     + b[j] * d[4 + 4 * nt + 2 * j])     * inv[j];
                float o1 = (a[j] * acc[nt][2 * j + 1] + b[j] * d[4 + 4 * nt + 2 * j + 1]) * inv[j];
                size_t off = (size_t)row * DIM + col0 + nt * 8 + 2 * (lane & 3);
                *(uint32_t*)(Of + off) = packh(o0, o1);
            }
        }
    }
}

// ======================= launch =======================
extern "C" void kernel_launch(void* const* d_in, const int* in_sizes, int n_in,
                              void* d_out, int out_size) {
    const float* x     = (const float*)d_in[0];
    const float* freqs = (const float*)d_in[1];
    const float* q_w   = (const float*)d_in[2];
    const float* q_b   = (const float*)d_in[3];
    const float* k_w   = (const float*)d_in[4];
    const float* k_b   = (const float*)d_in[5];
    const float* v_w   = (const float*)d_in[6];
    const float* v_b   = (const float*)d_in[7];
    const float* o_w   = (const float*)d_in[8];
    const float* o_b   = (const float*)d_in[9];
    const float* nqw   = (const float*)d_in[10];
    const float* nkw   = (const float*)d_in[11];

    float *gq, *gk;
    __half *xf, *qf, *kf, *vf, *of, *wf;
    cudaGetSymbolAddress((void**)&gq, g_q);
    cudaGetSymbolAddress((void**)&gk, g_k);
    cudaGetSymbolAddress((void**)&xf, g_xf);
    cudaGetSymbolAddress((void**)&qf, g_qf);
    cudaGetSymbolAddress((void**)&kf, g_kf);
    cudaGetSymbolAddress((void**)&vf, g_vf);
    cudaGetSymbolAddress((void**)&of, g_of);
    cudaGetSymbolAddress((void**)&wf, g_wf);

    const size_t WSZ = (size_t)DIM * DIM;
    __half* owf = wf + 3 * WSZ;

    split_all<<<dim3((NX4 + 255) / 256, 5), 256>>>(x, q_w, k_w, v_w, o_w, xf, wf);

    cudaFuncSetAttribute(gemm_qkv, cudaFuncAttributeMaxDynamicSharedMemorySize,
                         GEMM_SMEM_BYTES);
    cudaFuncSetAttribute(gemm_o, cudaFuncAttributeMaxDynamicSharedMemorySize,
                         GEMM_SMEM_BYTES);
    gemm_qkv<<<dim3(DIM / 128, TS / 128, 3), 256, GEMM_SMEM_BYTES>>>(
        xf, wf, q_b, k_b, v_b, gq, gk, vf);

    norm_rope_kernel<<<dim3(TS, 2), 256>>>(gq, gk, freqs, nqw, nkw, qf, kf);

    cudaFuncSetAttribute(attn_mma, cudaFuncAttributeMaxDynamicSharedMemorySize,
                         ATT_SMEM_BYTES);
    attn_mma<<<dim3(TS / AQB, NH), 256, ATT_SMEM_BYTES>>>(qf, kf, vf, of);

    gemm_o<<<dim3(DIM / 128, TS / 128), 256, GEMM_SMEM_BYTES>>>(
        of, owf, o_b, (float*)d_out);
}